// round 2
// baseline (speedup 1.0000x reference)
#include <cuda_runtime.h>
#include <math.h>

// ---------------- model constants ----------------
#define BVAL   32
#define DVAL   768
#define NTOK   197
#define NPATCH 196
#define HEADS  12
#define DKV    64
#define MLPD   3072
#define DEPTH  12
#define MTOK   (BVAL*NTOK)     // 6304
#define MPATCH (BVAL*NPATCH)   // 6272
#define NNSC   (NTOK*NTOK)     // 38809

// ---------------- scratch (static device globals; no allocation) ----------------
__device__ float g_tok[MTOK*DVAL];
__device__ float g_hbuf[MTOK*DVAL];
__device__ float g_q[MTOK*DVAL];
__device__ float g_k[MTOK*DVAL];
__device__ float g_v[MTOK*DVAL];
__device__ float g_ctx[MTOK*DVAL];                 // also reused as patch-conv output
__device__ float g_scores[(long long)BVAL*HEADS*NNSC];
__device__ float g_hid[(long long)MTOK*MLPD];
__device__ float g_col[(long long)MPATCH*DVAL];
__device__ float g_wT[DVAL*DVAL];

__device__ __forceinline__ float gelu_f(float x) {
    return 0.5f * x * (1.0f + erff(x * 0.70710678118654752440f));
}

// ---------------- generic batched SGEMM ----------------
// C[M,N] = op(epilogue)(A[M,K] @ B) ; B is [K,N] row-major (TRANSB=0) or accessed
// as B[n*ldb+k] (TRANSB=1). Batch offset = (z/hdiv)*s?0 + (z%hdiv)*s?1.
// EPI: 0 = store acc ; 1 = store acc+bias ; 2 = store gelu(acc+bias) ; 3 = C += acc+bias
template<int EPI, int TRANSB>
__global__ __launch_bounds__(256)
void sgemm_kernel(int M, int N, int K,
                  const float* __restrict__ A, int lda, long long sA0, long long sA1,
                  const float* __restrict__ Bm, int ldb, long long sB0, long long sB1,
                  float* __restrict__ C, int ldc, long long sC0, long long sC1,
                  const float* __restrict__ bias, int hdiv)
{
    __shared__ float As[16][132];
    __shared__ float Bs[16][132];

    int z  = blockIdx.z;
    int zb = z / hdiv, zh = z - zb * hdiv;
    A  += zb * sA0 + zh * sA1;
    Bm += zb * sB0 + zh * sB1;
    C  += zb * sC0 + zh * sC1;

    int tid = threadIdx.x;
    int tx = tid & 15, ty = tid >> 4;
    int row0 = blockIdx.y * 128, col0 = blockIdx.x * 128;

    float acc[8][8];
    #pragma unroll
    for (int i = 0; i < 8; i++)
        #pragma unroll
        for (int j = 0; j < 8; j++) acc[i][j] = 0.f;

    for (int k0 = 0; k0 < K; k0 += 16) {
        // load A tile (128 rows x 16 k), store transposed As[k][m]
        #pragma unroll
        for (int i = 0; i < 8; i++) {
            int e = tid + i * 256;
            int m = e >> 4, kk = e & 15;
            int gm = row0 + m, gk = k0 + kk;
            float v = 0.f;
            if (gm < M && gk < K) v = A[(long long)gm * lda + gk];
            As[kk][m] = v;
        }
        // load B tile Bs[k][n]
        #pragma unroll
        for (int i = 0; i < 8; i++) {
            int e = tid + i * 256;
            if (TRANSB) {
                int n = e >> 4, kk = e & 15;
                int gn = col0 + n, gk = k0 + kk;
                float v = 0.f;
                if (gn < N && gk < K) v = Bm[(long long)gn * ldb + gk];
                Bs[kk][n] = v;
            } else {
                int n = e & 127, kk = e >> 7;
                int gn = col0 + n, gk = k0 + kk;
                float v = 0.f;
                if (gn < N && gk < K) v = Bm[(long long)gk * ldb + gn];
                Bs[kk][n] = v;
            }
        }
        __syncthreads();

        #pragma unroll
        for (int kk = 0; kk < 16; kk++) {
            float a[8], b[8];
            #pragma unroll
            for (int i = 0; i < 8; i++) a[i] = As[kk][ty * 8 + i];
            #pragma unroll
            for (int j = 0; j < 8; j++) b[j] = Bs[kk][tx * 8 + j];
            #pragma unroll
            for (int i = 0; i < 8; i++)
                #pragma unroll
                for (int j = 0; j < 8; j++)
                    acc[i][j] = fmaf(a[i], b[j], acc[i][j]);
        }
        __syncthreads();
    }

    #pragma unroll
    for (int i = 0; i < 8; i++) {
        int gm = row0 + ty * 8 + i;
        if (gm >= M) continue;
        #pragma unroll
        for (int j = 0; j < 8; j++) {
            int gn = col0 + tx * 8 + j;
            if (gn >= N) continue;
            float r = acc[i][j];
            if (EPI >= 1) r += bias[gn];
            if (EPI == 2) r = gelu_f(r);
            long long idx = (long long)gm * ldc + gn;
            if (EPI == 3) C[idx] += r;
            else          C[idx] = r;
        }
    }
}

// ---------------- LayerNorm (one block per row of 768) ----------------
__global__ void ln_kernel(const float* __restrict__ in, float* __restrict__ out,
                          const float* __restrict__ w, const float* __restrict__ b)
{
    __shared__ float red[256];
    int row = blockIdx.x;
    int tid = threadIdx.x;
    const float* x = in + (long long)row * DVAL;

    float v0 = x[tid], v1 = x[tid + 256], v2 = x[tid + 512];
    red[tid] = v0 + v1 + v2;
    __syncthreads();
    for (int o = 128; o > 0; o >>= 1) { if (tid < o) red[tid] += red[tid + o]; __syncthreads(); }
    float mu = red[0] * (1.0f / 768.0f);
    __syncthreads();

    float d0 = v0 - mu, d1 = v1 - mu, d2 = v2 - mu;
    red[tid] = d0 * d0 + d1 * d1 + d2 * d2;
    __syncthreads();
    for (int o = 128; o > 0; o >>= 1) { if (tid < o) red[tid] += red[tid + o]; __syncthreads(); }
    float rs = rsqrtf(red[0] * (1.0f / 768.0f) + 1e-5f);

    float* y = out + (long long)row * DVAL;
    y[tid]       = d0 * rs * w[tid]       + b[tid];
    y[tid + 256] = d1 * rs * w[tid + 256] + b[tid + 256];
    y[tid + 512] = d2 * rs * w[tid + 512] + b[tid + 512];
}

// ---------------- softmax over last dim (197), warp per row; scale folded in ----------------
__global__ void softmax_kernel(float* __restrict__ s)
{
    int row = blockIdx.x * 8 + (threadIdx.x >> 5);
    if (row >= BVAL * HEADS * NTOK) return;
    int lane = threadIdx.x & 31;
    float* p = s + (long long)row * NTOK;
    const float scale = 0.125f;   // 1/sqrt(64)

    float vals[7];
    float mx = -1e30f;
    #pragma unroll
    for (int i = 0; i < 7; i++) {
        int c = lane + i * 32;
        float v = (c < NTOK) ? p[c] * scale : -1e30f;
        vals[i] = v;
        mx = fmaxf(mx, v);
    }
    #pragma unroll
    for (int o = 16; o > 0; o >>= 1) mx = fmaxf(mx, __shfl_xor_sync(0xffffffffu, mx, o));

    float sum = 0.f;
    #pragma unroll
    for (int i = 0; i < 7; i++) {
        int c = lane + i * 32;
        float e = (c < NTOK) ? expf(vals[i] - mx) : 0.f;
        vals[i] = e;
        sum += e;
    }
    #pragma unroll
    for (int o = 16; o > 0; o >>= 1) sum += __shfl_xor_sync(0xffffffffu, sum, o);
    float inv = 1.0f / sum;

    #pragma unroll
    for (int i = 0; i < 7; i++) {
        int c = lane + i * 32;
        if (c < NTOK) p[c] = vals[i] * inv;
    }
}

// ---------------- patch-embed helpers ----------------
__global__ void transpose_w_kernel(const float* __restrict__ w)  // [768out,768in] -> [768in,768out]
{
    int idx = blockIdx.x * 256 + threadIdx.x;
    if (idx >= DVAL * DVAL) return;
    int k = idx / DVAL, n = idx % DVAL;
    g_wT[k * DVAL + n] = w[n * DVAL + k];
}

__global__ void im2col_kernel(const float* __restrict__ x)  // x [B,3,224,224]
{
    long long idx = (long long)blockIdx.x * blockDim.x + threadIdx.x;
    if (idx >= (long long)MPATCH * DVAL) return;
    int col = (int)(idx % DVAL);
    long long r = idx / DVAL;
    int p = (int)(r % NPATCH);
    int b = (int)(r / NPATCH);
    int c = col >> 8;
    int rem = col & 255;
    int i = rem >> 4, j = rem & 15;
    int py = p / 14, px = p % 14;
    g_col[idx] = x[(((long long)b * 3 + c) * 224 + py * 16 + i) * 224 + px * 16 + j];
}

__global__ void assemble_tok_kernel(const float* __restrict__ patch,
                                    const float* __restrict__ cls,
                                    const float* __restrict__ pos)
{
    long long idx = (long long)blockIdx.x * blockDim.x + threadIdx.x;
    if (idx >= (long long)MTOK * DVAL) return;
    int d = (int)(idx % DVAL);
    long long r = idx / DVAL;
    int n = (int)(r % NTOK);
    int b = (int)(r / NTOK);
    float v;
    if (n == 0) v = cls[d];
    else        v = patch[((long long)b * NPATCH + (n - 1)) * DVAL + d];
    g_tok[idx] = v + pos[n * DVAL + d];
}

// ---------------- head: double-LN on cls + MLP head, one block per batch ----------------
__global__ void head_kernel(const float* __restrict__ tok,
                            const float* __restrict__ fw, const float* __restrict__ fb,
                            const float* __restrict__ hw, const float* __restrict__ hb,
                            const float* __restrict__ h1w, const float* __restrict__ h1b,
                            const float* __restrict__ h2w, const float* __restrict__ h2b,
                            float* __restrict__ out)
{
    __shared__ float cbuf[DVAL];
    __shared__ float hid[MLPD];
    __shared__ float red[256];
    int b = blockIdx.x, tid = threadIdx.x;
    const float* t = tok + (long long)b * NTOK * DVAL;   // cls row

    // ----- LN (fnorm) -----
    float v0 = t[tid], v1 = t[tid + 256], v2 = t[tid + 512];
    red[tid] = v0 + v1 + v2; __syncthreads();
    for (int o = 128; o > 0; o >>= 1) { if (tid < o) red[tid] += red[tid + o]; __syncthreads(); }
    float mu = red[0] * (1.0f / 768.0f); __syncthreads();
    float d0 = v0 - mu, d1 = v1 - mu, d2 = v2 - mu;
    red[tid] = d0 * d0 + d1 * d1 + d2 * d2; __syncthreads();
    for (int o = 128; o > 0; o >>= 1) { if (tid < o) red[tid] += red[tid + o]; __syncthreads(); }
    float rs = rsqrtf(red[0] * (1.0f / 768.0f) + 1e-5f); __syncthreads();
    float u0 = d0 * rs * fw[tid]       + fb[tid];
    float u1 = d1 * rs * fw[tid + 256] + fb[tid + 256];
    float u2 = d2 * rs * fw[tid + 512] + fb[tid + 512];

    // ----- LN (hln) -----
    red[tid] = u0 + u1 + u2; __syncthreads();
    for (int o = 128; o > 0; o >>= 1) { if (tid < o) red[tid] += red[tid + o]; __syncthreads(); }
    mu = red[0] * (1.0f / 768.0f); __syncthreads();
    d0 = u0 - mu; d1 = u1 - mu; d2 = u2 - mu;
    red[tid] = d0 * d0 + d1 * d1 + d2 * d2; __syncthreads();
    for (int o = 128; o > 0; o >>= 1) { if (tid < o) red[tid] += red[tid + o]; __syncthreads(); }
    rs = rsqrtf(red[0] * (1.0f / 768.0f) + 1e-5f); __syncthreads();
    cbuf[tid]       = d0 * rs * hw[tid]       + hb[tid];
    cbuf[tid + 256] = d1 * rs * hw[tid + 256] + hb[tid + 256];
    cbuf[tid + 512] = d2 * rs * hw[tid + 512] + hb[tid + 512];
    __syncthreads();

    // ----- hidden = gelu(c @ h1w + h1b), h1w [768,3072] -----
    for (int j = tid; j < MLPD; j += 256) {
        float sacc = h1b[j];
        for (int d = 0; d < DVAL; d++)
            sacc = fmaf(cbuf[d], h1w[(long long)d * MLPD + j], sacc);
        hid[j] = gelu_f(sacc);
    }
    __syncthreads();

    // ----- logits = hid @ h2w + h2b, h2w [3072,2] -----
    for (int c2 = 0; c2 < 2; c2++) {
        float part = 0.f;
        for (int j = tid; j < MLPD; j += 256)
            part = fmaf(hid[j], h2w[j * 2 + c2], part);
        red[tid] = part; __syncthreads();
        for (int o = 128; o > 0; o >>= 1) { if (tid < o) red[tid] += red[tid + o]; __syncthreads(); }
        if (tid == 0) out[b * 2 + c2] = red[0] + h2b[c2];
        __syncthreads();
    }
}

// ---------------- host-side GEMM dispatch ----------------
static void launch_gemm(int epi, int transb, int M, int N, int K,
                        const float* A, int lda, long long sA0, long long sA1,
                        const float* Bm, int ldb, long long sB0, long long sB1,
                        float* C, int ldc, long long sC0, long long sC1,
                        const float* bias, int batch, int hdiv)
{
    dim3 grid((N + 127) / 128, (M + 127) / 128, batch), blk(256);
#define GEMM_CALL(E, T) sgemm_kernel<E, T><<<grid, blk>>>(M, N, K, A, lda, sA0, sA1, Bm, ldb, sB0, sB1, C, ldc, sC0, sC1, bias, hdiv)
    if (transb == 0) {
        if      (epi == 0) GEMM_CALL(0, 0);
        else if (epi == 1) GEMM_CALL(1, 0);
        else if (epi == 2) GEMM_CALL(2, 0);
        else               GEMM_CALL(3, 0);
    } else {
        if      (epi == 0) GEMM_CALL(0, 1);
        else if (epi == 1) GEMM_CALL(1, 1);
        else if (epi == 2) GEMM_CALL(2, 1);
        else               GEMM_CALL(3, 1);
    }
#undef GEMM_CALL
}

extern "C" void kernel_launch(void* const* d_in, const int* in_sizes, int n_in,
                              void* d_out, int out_size)
{
    const float* x         = (const float*)d_in[0];
    const float* conv_w    = (const float*)d_in[1];
    const float* conv_b    = (const float*)d_in[2];
    const float* cls_token = (const float*)d_in[3];
    const float* pos_embed = (const float*)d_in[4];
    const float* ln1_w     = (const float*)d_in[5];
    const float* ln1_b     = (const float*)d_in[6];
    const float* wq        = (const float*)d_in[7];
    const float* wk        = (const float*)d_in[8];
    const float* wv        = (const float*)d_in[9];
    const float* wo_w      = (const float*)d_in[10];
    const float* wo_b      = (const float*)d_in[11];
    const float* ln2_w     = (const float*)d_in[12];
    const float* ln2_b     = (const float*)d_in[13];
    const float* mlp1_w    = (const float*)d_in[14];
    const float* mlp1_b    = (const float*)d_in[15];
    const float* mlp2_w    = (const float*)d_in[16];
    const float* mlp2_b    = (const float*)d_in[17];
    const float* fnorm_w   = (const float*)d_in[18];
    const float* fnorm_b   = (const float*)d_in[19];
    const float* hln_w     = (const float*)d_in[20];
    const float* hln_b     = (const float*)d_in[21];
    const float* h1_w      = (const float*)d_in[22];
    const float* h1_b      = (const float*)d_in[23];
    const float* h2_w      = (const float*)d_in[24];
    const float* h2_b      = (const float*)d_in[25];

    float *tokp, *hp, *qp, *kp, *vp, *ctxp, *scp, *hidp, *colp, *wtp;
    cudaGetSymbolAddress((void**)&tokp, g_tok);
    cudaGetSymbolAddress((void**)&hp,   g_hbuf);
    cudaGetSymbolAddress((void**)&qp,   g_q);
    cudaGetSymbolAddress((void**)&kp,   g_k);
    cudaGetSymbolAddress((void**)&vp,   g_v);
    cudaGetSymbolAddress((void**)&ctxp, g_ctx);
    cudaGetSymbolAddress((void**)&scp,  g_scores);
    cudaGetSymbolAddress((void**)&hidp, g_hid);
    cudaGetSymbolAddress((void**)&colp, g_col);
    cudaGetSymbolAddress((void**)&wtp,  g_wT);

    // ---- patch embed: im2col + GEMM(gelu+bias) + token assembly ----
    transpose_w_kernel<<<(DVAL * DVAL + 255) / 256, 256>>>(conv_w);
    im2col_kernel<<<(int)(((long long)MPATCH * DVAL + 255) / 256), 256>>>(x);
    launch_gemm(2, 0, MPATCH, DVAL, DVAL,
                colp, DVAL, 0, 0, wtp, DVAL, 0, 0, ctxp, DVAL, 0, 0,
                conv_b, 1, 1);
    assemble_tok_kernel<<<(int)(((long long)MTOK * DVAL + 255) / 256), 256>>>(ctxp, cls_token, pos_embed);

    const long long D2 = (long long)DVAL * DVAL;
    const long long DM = (long long)DVAL * MLPD;

    for (int L = 0; L < DEPTH; L++) {
        // LN1
        ln_kernel<<<MTOK, 256>>>(tokp, hp, ln1_w + L * DVAL, ln1_b + L * DVAL);
        // Q, K, V (no bias)
        launch_gemm(0, 0, MTOK, DVAL, DVAL, hp, DVAL, 0, 0, wq + L * D2, DVAL, 0, 0, qp, DVAL, 0, 0, nullptr, 1, 1);
        launch_gemm(0, 0, MTOK, DVAL, DVAL, hp, DVAL, 0, 0, wk + L * D2, DVAL, 0, 0, kp, DVAL, 0, 0, nullptr, 1, 1);
        launch_gemm(0, 0, MTOK, DVAL, DVAL, hp, DVAL, 0, 0, wv + L * D2, DVAL, 0, 0, vp, DVAL, 0, 0, nullptr, 1, 1);
        // scores = Q @ K^T  (batched over B*H; scale folded into softmax)
        launch_gemm(0, 1, NTOK, NTOK, DKV,
                    qp, DVAL, (long long)NTOK * DVAL, DKV,
                    kp, DVAL, (long long)NTOK * DVAL, DKV,
                    scp, NTOK, (long long)HEADS * NNSC, NNSC,
                    nullptr, BVAL * HEADS, HEADS);
        softmax_kernel<<<(BVAL * HEADS * NTOK) / 8, 256>>>(scp);
        // ctx = attn @ V (batched)
        launch_gemm(0, 0, NTOK, DKV, NTOK,
                    scp, NTOK, (long long)HEADS * NNSC, NNSC,
                    vp, DVAL, (long long)NTOK * DVAL, DKV,
                    ctxp, DVAL, (long long)NTOK * DVAL, DKV,
                    nullptr, BVAL * HEADS, HEADS);
        // tok += ctx @ Wo + bo
        launch_gemm(3, 0, MTOK, DVAL, DVAL, ctxp, DVAL, 0, 0, wo_w + L * D2, DVAL, 0, 0,
                    tokp, DVAL, 0, 0, wo_b + L * DVAL, 1, 1);
        // LN2
        ln_kernel<<<MTOK, 256>>>(tokp, hp, ln2_w + L * DVAL, ln2_b + L * DVAL);
        // hid = gelu(h @ W1 + b1)
        launch_gemm(2, 0, MTOK, MLPD, DVAL, hp, DVAL, 0, 0, mlp1_w + L * DM, MLPD, 0, 0,
                    hidp, MLPD, 0, 0, mlp1_b + L * MLPD, 1, 1);
        // tok += hid @ W2 + b2
        launch_gemm(3, 0, MTOK, DVAL, MLPD, hidp, MLPD, 0, 0, mlp2_w + L * DM, DVAL, 0, 0,
                    tokp, DVAL, 0, 0, mlp2_b + L * DVAL, 1, 1);
    }

    head_kernel<<<BVAL, 256>>>(tokp, fnorm_w, fnorm_b, hln_w, hln_b,
                               h1_w, h1_b, h2_w, h2_b, (float*)d_out);
}

// round 3
// speedup vs baseline: 3.0013x; 3.0013x over previous
#include <cuda_runtime.h>
#include <math.h>
#include <stdint.h>

// ---------------- model constants ----------------
#define BVAL   32
#define DVAL   768
#define NTOK   197
#define NPATCH 196
#define HEADS  12
#define DKV    64
#define MLPD   3072
#define DEPTH  12
#define MTOK   (BVAL*NTOK)     // 6304
#define MPATCH (BVAL*NPATCH)   // 6272
#define NNSC   (NTOK*NTOK)     // 38809

// ---------------- scratch (static device globals; no allocation) ----------------
__device__ float g_tok[MTOK*DVAL];
__device__ float g_hbuf[MTOK*DVAL];
__device__ float g_q[MTOK*DVAL];
__device__ float g_k[MTOK*DVAL];
__device__ float g_v[MTOK*DVAL];
__device__ float g_ctx[MTOK*DVAL];                 // also reused as patch-conv output
__device__ float g_scores[(long long)BVAL*HEADS*NNSC];
__device__ float g_hid[(long long)MTOK*MLPD];
__device__ float g_col[(long long)MPATCH*DVAL];
__device__ float g_wT[DVAL*DVAL];

__device__ __forceinline__ float gelu_f(float x) {
    return 0.5f * x * (1.0f + erff(x * 0.70710678118654752440f));
}

__device__ __forceinline__ uint32_t tf32_cvt(float x) {
    uint32_t r;
    asm("cvt.rna.tf32.f32 %0, %1;" : "=r"(r) : "f"(x));
    return r;
}

// =========================================================================
// tf32 tensor-core GEMM: C[M,N] = epi(A[M,K] @ B[K,N])
// Requirements: K % 16 == 0, N % 128 == 0 (bounds-checked on M only).
// Block 128x128, 8 warps of 64x32, mma.m16n8k8.tf32, double-buffered smem.
// EPI: 0 = store ; 2 = store gelu(acc+bias) ; 3 = C += acc+bias
// =========================================================================
#define AS_STRIDE 20
#define BS_STRIDE 136

template<int EPI>
__global__ __launch_bounds__(256)
void tf32gemm_kernel(int M, int N, int K,
                     const float* __restrict__ A, int lda,
                     const float* __restrict__ B, int ldb,
                     float* __restrict__ C, int ldc,
                     const float* __restrict__ bias)
{
    __shared__ float As[2][128 * AS_STRIDE];
    __shared__ float Bs[2][16 * BS_STRIDE];

    const int tid  = threadIdx.x;
    const int wid  = tid >> 5, lane = tid & 31;
    const int warpM = wid >> 2, warpN = wid & 3;
    const int quad = lane & 3, gid = lane >> 2;
    const int row0 = blockIdx.y * 128, col0 = blockIdx.x * 128;

    float acc[4][4][4];
    #pragma unroll
    for (int i = 0; i < 4; i++)
        #pragma unroll
        for (int j = 0; j < 4; j++)
            #pragma unroll
            for (int r = 0; r < 4; r++) acc[i][j][r] = 0.f;

    // per-thread global-load coordinates (2 float4 each for A and B tiles)
    int aR[2], aC[2], bR[2], bC[2];
    #pragma unroll
    for (int i = 0; i < 2; i++) {
        int e = tid + i * 256;
        aR[i] = e >> 2;  aC[i] = (e & 3) * 4;   // A tile: 128 rows x 16 k
        bR[i] = e >> 5;  bC[i] = (e & 31) * 4;  // B tile: 16 k x 128 n
    }

    const int nk = K / 16;
    float4 va[2], vb[2];

    // ---- load tile 0 ----
    #pragma unroll
    for (int i = 0; i < 2; i++) {
        int gm = row0 + aR[i];
        va[i] = (gm < M) ? *(const float4*)(A + (size_t)gm * lda + aC[i])
                         : make_float4(0.f, 0.f, 0.f, 0.f);
        vb[i] = *(const float4*)(B + (size_t)bR[i] * ldb + col0 + bC[i]);
    }
    #pragma unroll
    for (int i = 0; i < 2; i++) {
        float* ap = &As[0][aR[i] * AS_STRIDE + aC[i]];
        ap[0] = __uint_as_float(tf32_cvt(va[i].x));
        ap[1] = __uint_as_float(tf32_cvt(va[i].y));
        ap[2] = __uint_as_float(tf32_cvt(va[i].z));
        ap[3] = __uint_as_float(tf32_cvt(va[i].w));
        float* bp = &Bs[0][bR[i] * BS_STRIDE + bC[i]];
        bp[0] = __uint_as_float(tf32_cvt(vb[i].x));
        bp[1] = __uint_as_float(tf32_cvt(vb[i].y));
        bp[2] = __uint_as_float(tf32_cvt(vb[i].z));
        bp[3] = __uint_as_float(tf32_cvt(vb[i].w));
    }
    __syncthreads();

    for (int kt = 0; kt < nk; kt++) {
        const int cur = kt & 1;
        const bool more = (kt + 1 < nk);
        // prefetch next tile into registers
        if (more) {
            int k0 = (kt + 1) * 16;
            #pragma unroll
            for (int i = 0; i < 2; i++) {
                int gm = row0 + aR[i];
                va[i] = (gm < M) ? *(const float4*)(A + (size_t)gm * lda + k0 + aC[i])
                                 : make_float4(0.f, 0.f, 0.f, 0.f);
                vb[i] = *(const float4*)(B + (size_t)(k0 + bR[i]) * ldb + col0 + bC[i]);
            }
        }

        // compute on buffer cur
        const float* as = As[cur];
        const float* bs = Bs[cur];
        #pragma unroll
        for (int ks = 0; ks < 16; ks += 8) {
            uint32_t afr[4][4], bfr[4][2];
            #pragma unroll
            for (int ni = 0; ni < 4; ni++) {
                int cb = warpN * 32 + ni * 8 + gid;
                bfr[ni][0] = __float_as_uint(bs[(ks + quad)     * BS_STRIDE + cb]);
                bfr[ni][1] = __float_as_uint(bs[(ks + 4 + quad) * BS_STRIDE + cb]);
            }
            #pragma unroll
            for (int mi = 0; mi < 4; mi++) {
                int rb = warpM * 64 + mi * 16;
                afr[mi][0] = __float_as_uint(as[(rb + gid)     * AS_STRIDE + ks + quad]);
                afr[mi][1] = __float_as_uint(as[(rb + 8 + gid) * AS_STRIDE + ks + quad]);
                afr[mi][2] = __float_as_uint(as[(rb + gid)     * AS_STRIDE + ks + 4 + quad]);
                afr[mi][3] = __float_as_uint(as[(rb + 8 + gid) * AS_STRIDE + ks + 4 + quad]);
            }
            #pragma unroll
            for (int mi = 0; mi < 4; mi++)
                #pragma unroll
                for (int ni = 0; ni < 4; ni++) {
                    asm volatile(
                        "mma.sync.aligned.m16n8k8.row.col.f32.tf32.tf32.f32 "
                        "{%0,%1,%2,%3}, {%4,%5,%6,%7}, {%8,%9}, {%0,%1,%2,%3};"
                        : "+f"(acc[mi][ni][0]), "+f"(acc[mi][ni][1]),
                          "+f"(acc[mi][ni][2]), "+f"(acc[mi][ni][3])
                        : "r"(afr[mi][0]), "r"(afr[mi][1]), "r"(afr[mi][2]), "r"(afr[mi][3]),
                          "r"(bfr[ni][0]), "r"(bfr[ni][1]));
                }
        }

        // store prefetched tile into the other buffer
        if (more) {
            const int nxt = cur ^ 1;
            #pragma unroll
            for (int i = 0; i < 2; i++) {
                float* ap = &As[nxt][aR[i] * AS_STRIDE + aC[i]];
                ap[0] = __uint_as_float(tf32_cvt(va[i].x));
                ap[1] = __uint_as_float(tf32_cvt(va[i].y));
                ap[2] = __uint_as_float(tf32_cvt(va[i].z));
                ap[3] = __uint_as_float(tf32_cvt(va[i].w));
                float* bp = &Bs[nxt][bR[i] * BS_STRIDE + bC[i]];
                bp[0] = __uint_as_float(tf32_cvt(vb[i].x));
                bp[1] = __uint_as_float(tf32_cvt(vb[i].y));
                bp[2] = __uint_as_float(tf32_cvt(vb[i].z));
                bp[3] = __uint_as_float(tf32_cvt(vb[i].w));
            }
            __syncthreads();
        }
    }

    // ---- epilogue ----
    #pragma unroll
    for (int mi = 0; mi < 4; mi++) {
        int r0 = row0 + warpM * 64 + mi * 16 + gid;
        int r1 = r0 + 8;
        #pragma unroll
        for (int ni = 0; ni < 4; ni++) {
            int c = col0 + warpN * 32 + ni * 8 + 2 * quad;
            float b0 = 0.f, b1 = 0.f;
            if (EPI >= 2) { b0 = bias[c]; b1 = bias[c + 1]; }
            if (r0 < M) {
                float x0 = acc[mi][ni][0] + b0, x1 = acc[mi][ni][1] + b1;
                if (EPI == 2) { x0 = gelu_f(x0); x1 = gelu_f(x1); }
                size_t idx = (size_t)r0 * ldc + c;
                if (EPI == 3) { C[idx] += x0; C[idx + 1] += x1; }
                else          { C[idx] = x0;  C[idx + 1] = x1; }
            }
            if (r1 < M) {
                float x0 = acc[mi][ni][2] + b0, x1 = acc[mi][ni][3] + b1;
                if (EPI == 2) { x0 = gelu_f(x0); x1 = gelu_f(x1); }
                size_t idx = (size_t)r1 * ldc + c;
                if (EPI == 3) { C[idx] += x0; C[idx + 1] += x1; }
                else          { C[idx] = x0;  C[idx + 1] = x1; }
            }
        }
    }
}

static void launch_tf32(int epi, int M, int N, int K,
                        const float* A, int lda, const float* B, int ldb,
                        float* C, int ldc, const float* bias)
{
    dim3 grid(N / 128, (M + 127) / 128), blk(256);
    if      (epi == 0) tf32gemm_kernel<0><<<grid, blk>>>(M, N, K, A, lda, B, ldb, C, ldc, bias);
    else if (epi == 2) tf32gemm_kernel<2><<<grid, blk>>>(M, N, K, A, lda, B, ldb, C, ldc, bias);
    else               tf32gemm_kernel<3><<<grid, blk>>>(M, N, K, A, lda, B, ldb, C, ldc, bias);
}

// ---------------- generic batched fp32 SGEMM (attention only now) ----------------
template<int EPI, int TRANSB>
__global__ __launch_bounds__(256)
void sgemm_kernel(int M, int N, int K,
                  const float* __restrict__ A, int lda, long long sA0, long long sA1,
                  const float* __restrict__ Bm, int ldb, long long sB0, long long sB1,
                  float* __restrict__ C, int ldc, long long sC0, long long sC1,
                  const float* __restrict__ bias, int hdiv)
{
    __shared__ float As[16][132];
    __shared__ float Bs[16][132];

    int z  = blockIdx.z;
    int zb = z / hdiv, zh = z - zb * hdiv;
    A  += zb * sA0 + zh * sA1;
    Bm += zb * sB0 + zh * sB1;
    C  += zb * sC0 + zh * sC1;

    int tid = threadIdx.x;
    int tx = tid & 15, ty = tid >> 4;
    int row0 = blockIdx.y * 128, col0 = blockIdx.x * 128;

    float acc[8][8];
    #pragma unroll
    for (int i = 0; i < 8; i++)
        #pragma unroll
        for (int j = 0; j < 8; j++) acc[i][j] = 0.f;

    for (int k0 = 0; k0 < K; k0 += 16) {
        #pragma unroll
        for (int i = 0; i < 8; i++) {
            int e = tid + i * 256;
            int m = e >> 4, kk = e & 15;
            int gm = row0 + m, gk = k0 + kk;
            float v = 0.f;
            if (gm < M && gk < K) v = A[(long long)gm * lda + gk];
            As[kk][m] = v;
        }
        #pragma unroll
        for (int i = 0; i < 8; i++) {
            int e = tid + i * 256;
            if (TRANSB) {
                int n = e >> 4, kk = e & 15;
                int gn = col0 + n, gk = k0 + kk;
                float v = 0.f;
                if (gn < N && gk < K) v = Bm[(long long)gn * ldb + gk];
                Bs[kk][n] = v;
            } else {
                int n = e & 127, kk = e >> 7;
                int gn = col0 + n, gk = k0 + kk;
                float v = 0.f;
                if (gn < N && gk < K) v = Bm[(long long)gk * ldb + gn];
                Bs[kk][n] = v;
            }
        }
        __syncthreads();

        #pragma unroll
        for (int kk = 0; kk < 16; kk++) {
            float a[8], b[8];
            #pragma unroll
            for (int i = 0; i < 8; i++) a[i] = As[kk][ty * 8 + i];
            #pragma unroll
            for (int j = 0; j < 8; j++) b[j] = Bs[kk][tx * 8 + j];
            #pragma unroll
            for (int i = 0; i < 8; i++)
                #pragma unroll
                for (int j = 0; j < 8; j++)
                    acc[i][j] = fmaf(a[i], b[j], acc[i][j]);
        }
        __syncthreads();
    }

    #pragma unroll
    for (int i = 0; i < 8; i++) {
        int gm = row0 + ty * 8 + i;
        if (gm >= M) continue;
        #pragma unroll
        for (int j = 0; j < 8; j++) {
            int gn = col0 + tx * 8 + j;
            if (gn >= N) continue;
            float r = acc[i][j];
            if (EPI >= 1) r += bias[gn];
            if (EPI == 2) r = gelu_f(r);
            long long idx = (long long)gm * ldc + gn;
            if (EPI == 3) C[idx] += r;
            else          C[idx] = r;
        }
    }
}

// ---------------- LayerNorm (one block per row of 768) ----------------
__global__ void ln_kernel(const float* __restrict__ in, float* __restrict__ out,
                          const float* __restrict__ w, const float* __restrict__ b)
{
    __shared__ float red[256];
    int row = blockIdx.x;
    int tid = threadIdx.x;
    const float* x = in + (long long)row * DVAL;

    float v0 = x[tid], v1 = x[tid + 256], v2 = x[tid + 512];
    red[tid] = v0 + v1 + v2;
    __syncthreads();
    for (int o = 128; o > 0; o >>= 1) { if (tid < o) red[tid] += red[tid + o]; __syncthreads(); }
    float mu = red[0] * (1.0f / 768.0f);
    __syncthreads();

    float d0 = v0 - mu, d1 = v1 - mu, d2 = v2 - mu;
    red[tid] = d0 * d0 + d1 * d1 + d2 * d2;
    __syncthreads();
    for (int o = 128; o > 0; o >>= 1) { if (tid < o) red[tid] += red[tid + o]; __syncthreads(); }
    float rs = rsqrtf(red[0] * (1.0f / 768.0f) + 1e-5f);

    float* y = out + (long long)row * DVAL;
    y[tid]       = d0 * rs * w[tid]       + b[tid];
    y[tid + 256] = d1 * rs * w[tid + 256] + b[tid + 256];
    y[tid + 512] = d2 * rs * w[tid + 512] + b[tid + 512];
}

// ---------------- softmax over last dim (197), warp per row; scale folded in ----------------
__global__ void softmax_kernel(float* __restrict__ s)
{
    int row = blockIdx.x * 8 + (threadIdx.x >> 5);
    if (row >= BVAL * HEADS * NTOK) return;
    int lane = threadIdx.x & 31;
    float* p = s + (long long)row * NTOK;
    const float scale = 0.125f;   // 1/sqrt(64)

    float vals[7];
    float mx = -1e30f;
    #pragma unroll
    for (int i = 0; i < 7; i++) {
        int c = lane + i * 32;
        float v = (c < NTOK) ? p[c] * scale : -1e30f;
        vals[i] = v;
        mx = fmaxf(mx, v);
    }
    #pragma unroll
    for (int o = 16; o > 0; o >>= 1) mx = fmaxf(mx, __shfl_xor_sync(0xffffffffu, mx, o));

    float sum = 0.f;
    #pragma unroll
    for (int i = 0; i < 7; i++) {
        int c = lane + i * 32;
        float e = (c < NTOK) ? expf(vals[i] - mx) : 0.f;
        vals[i] = e;
        sum += e;
    }
    #pragma unroll
    for (int o = 16; o > 0; o >>= 1) sum += __shfl_xor_sync(0xffffffffu, sum, o);
    float inv = 1.0f / sum;

    #pragma unroll
    for (int i = 0; i < 7; i++) {
        int c = lane + i * 32;
        if (c < NTOK) p[c] = vals[i] * inv;
    }
}

// ---------------- patch-embed helpers ----------------
__global__ void transpose_w_kernel(const float* __restrict__ w)  // [768out,768in] -> [768in,768out]
{
    int idx = blockIdx.x * 256 + threadIdx.x;
    if (idx >= DVAL * DVAL) return;
    int k = idx / DVAL, n = idx % DVAL;
    g_wT[k * DVAL + n] = w[n * DVAL + k];
}

__global__ void im2col_kernel(const float* __restrict__ x)  // x [B,3,224,224]
{
    long long idx = (long long)blockIdx.x * blockDim.x + threadIdx.x;
    if (idx >= (long long)MPATCH * DVAL) return;
    int col = (int)(idx % DVAL);
    long long r = idx / DVAL;
    int p = (int)(r % NPATCH);
    int b = (int)(r / NPATCH);
    int c = col >> 8;
    int rem = col & 255;
    int i = rem >> 4, j = rem & 15;
    int py = p / 14, px = p % 14;
    g_col[idx] = x[(((long long)b * 3 + c) * 224 + py * 16 + i) * 224 + px * 16 + j];
}

__global__ void assemble_tok_kernel(const float* __restrict__ patch,
                                    const float* __restrict__ cls,
                                    const float* __restrict__ pos)
{
    long long idx = (long long)blockIdx.x * blockDim.x + threadIdx.x;
    if (idx >= (long long)MTOK * DVAL) return;
    int d = (int)(idx % DVAL);
    long long r = idx / DVAL;
    int n = (int)(r % NTOK);
    int b = (int)(r / NTOK);
    float v;
    if (n == 0) v = cls[d];
    else        v = patch[((long long)b * NPATCH + (n - 1)) * DVAL + d];
    g_tok[idx] = v + pos[n * DVAL + d];
}

// ---------------- head: double-LN on cls + MLP head, one block per batch ----------------
__global__ void head_kernel(const float* __restrict__ tok,
                            const float* __restrict__ fw, const float* __restrict__ fb,
                            const float* __restrict__ hw, const float* __restrict__ hb,
                            const float* __restrict__ h1w, const float* __restrict__ h1b,
                            const float* __restrict__ h2w, const float* __restrict__ h2b,
                            float* __restrict__ out)
{
    __shared__ float cbuf[DVAL];
    __shared__ float hid[MLPD];
    __shared__ float red[256];
    int b = blockIdx.x, tid = threadIdx.x;
    const float* t = tok + (long long)b * NTOK * DVAL;   // cls row

    float v0 = t[tid], v1 = t[tid + 256], v2 = t[tid + 512];
    red[tid] = v0 + v1 + v2; __syncthreads();
    for (int o = 128; o > 0; o >>= 1) { if (tid < o) red[tid] += red[tid + o]; __syncthreads(); }
    float mu = red[0] * (1.0f / 768.0f); __syncthreads();
    float d0 = v0 - mu, d1 = v1 - mu, d2 = v2 - mu;
    red[tid] = d0 * d0 + d1 * d1 + d2 * d2; __syncthreads();
    for (int o = 128; o > 0; o >>= 1) { if (tid < o) red[tid] += red[tid + o]; __syncthreads(); }
    float rs = rsqrtf(red[0] * (1.0f / 768.0f) + 1e-5f); __syncthreads();
    float u0 = d0 * rs * fw[tid]       + fb[tid];
    float u1 = d1 * rs * fw[tid + 256] + fb[tid + 256];
    float u2 = d2 * rs * fw[tid + 512] + fb[tid + 512];

    red[tid] = u0 + u1 + u2; __syncthreads();
    for (int o = 128; o > 0; o >>= 1) { if (tid < o) red[tid] += red[tid + o]; __syncthreads(); }
    mu = red[0] * (1.0f / 768.0f); __syncthreads();
    d0 = u0 - mu; d1 = u1 - mu; d2 = u2 - mu;
    red[tid] = d0 * d0 + d1 * d1 + d2 * d2; __syncthreads();
    for (int o = 128; o > 0; o >>= 1) { if (tid < o) red[tid] += red[tid + o]; __syncthreads(); }
    rs = rsqrtf(red[0] * (1.0f / 768.0f) + 1e-5f); __syncthreads();
    cbuf[tid]       = d0 * rs * hw[tid]       + hb[tid];
    cbuf[tid + 256] = d1 * rs * hw[tid + 256] + hb[tid + 256];
    cbuf[tid + 512] = d2 * rs * hw[tid + 512] + hb[tid + 512];
    __syncthreads();

    for (int j = tid; j < MLPD; j += 256) {
        float sacc = h1b[j];
        for (int d = 0; d < DVAL; d++)
            sacc = fmaf(cbuf[d], h1w[(long long)d * MLPD + j], sacc);
        hid[j] = gelu_f(sacc);
    }
    __syncthreads();

    for (int c2 = 0; c2 < 2; c2++) {
        float part = 0.f;
        for (int j = tid; j < MLPD; j += 256)
            part = fmaf(hid[j], h2w[j * 2 + c2], part);
        red[tid] = part; __syncthreads();
        for (int o = 128; o > 0; o >>= 1) { if (tid < o) red[tid] += red[tid + o]; __syncthreads(); }
        if (tid == 0) out[b * 2 + c2] = red[0] + h2b[c2];
        __syncthreads();
    }
}

// ---------------- host-side fp32 GEMM dispatch (attention) ----------------
static void launch_gemm(int epi, int transb, int M, int N, int K,
                        const float* A, int lda, long long sA0, long long sA1,
                        const float* Bm, int ldb, long long sB0, long long sB1,
                        float* C, int ldc, long long sC0, long long sC1,
                        const float* bias, int batch, int hdiv)
{
    dim3 grid((N + 127) / 128, (M + 127) / 128, batch), blk(256);
#define GEMM_CALL(E, T) sgemm_kernel<E, T><<<grid, blk>>>(M, N, K, A, lda, sA0, sA1, Bm, ldb, sB0, sB1, C, ldc, sC0, sC1, bias, hdiv)
    if (transb == 0) {
        if      (epi == 0) GEMM_CALL(0, 0);
        else if (epi == 1) GEMM_CALL(1, 0);
        else if (epi == 2) GEMM_CALL(2, 0);
        else               GEMM_CALL(3, 0);
    } else {
        if      (epi == 0) GEMM_CALL(0, 1);
        else if (epi == 1) GEMM_CALL(1, 1);
        else if (epi == 2) GEMM_CALL(2, 1);
        else               GEMM_CALL(3, 1);
    }
#undef GEMM_CALL
}

extern "C" void kernel_launch(void* const* d_in, const int* in_sizes, int n_in,
                              void* d_out, int out_size)
{
    const float* x         = (const float*)d_in[0];
    const float* conv_w    = (const float*)d_in[1];
    const float* conv_b    = (const float*)d_in[2];
    const float* cls_token = (const float*)d_in[3];
    const float* pos_embed = (const float*)d_in[4];
    const float* ln1_w     = (const float*)d_in[5];
    const float* ln1_b     = (const float*)d_in[6];
    const float* wq        = (const float*)d_in[7];
    const float* wk        = (const float*)d_in[8];
    const float* wv        = (const float*)d_in[9];
    const float* wo_w      = (const float*)d_in[10];
    const float* wo_b      = (const float*)d_in[11];
    const float* ln2_w     = (const float*)d_in[12];
    const float* ln2_b     = (const float*)d_in[13];
    const float* mlp1_w    = (const float*)d_in[14];
    const float* mlp1_b    = (const float*)d_in[15];
    const float* mlp2_w    = (const float*)d_in[16];
    const float* mlp2_b    = (const float*)d_in[17];
    const float* fnorm_w   = (const float*)d_in[18];
    const float* fnorm_b   = (const float*)d_in[19];
    const float* hln_w     = (const float*)d_in[20];
    const float* hln_b     = (const float*)d_in[21];
    const float* h1_w      = (const float*)d_in[22];
    const float* h1_b      = (const float*)d_in[23];
    const float* h2_w      = (const float*)d_in[24];
    const float* h2_b      = (const float*)d_in[25];

    float *tokp, *hp, *qp, *kp, *vp, *ctxp, *scp, *hidp, *colp, *wtp;
    cudaGetSymbolAddress((void**)&tokp, g_tok);
    cudaGetSymbolAddress((void**)&hp,   g_hbuf);
    cudaGetSymbolAddress((void**)&qp,   g_q);
    cudaGetSymbolAddress((void**)&kp,   g_k);
    cudaGetSymbolAddress((void**)&vp,   g_v);
    cudaGetSymbolAddress((void**)&ctxp, g_ctx);
    cudaGetSymbolAddress((void**)&scp,  g_scores);
    cudaGetSymbolAddress((void**)&hidp, g_hid);
    cudaGetSymbolAddress((void**)&colp, g_col);
    cudaGetSymbolAddress((void**)&wtp,  g_wT);

    // ---- patch embed: im2col + tf32 GEMM(gelu+bias) + token assembly ----
    transpose_w_kernel<<<(DVAL * DVAL + 255) / 256, 256>>>(conv_w);
    im2col_kernel<<<(int)(((long long)MPATCH * DVAL + 255) / 256), 256>>>(x);
    launch_tf32(2, MPATCH, DVAL, DVAL, colp, DVAL, wtp, DVAL, ctxp, DVAL, conv_b);
    assemble_tok_kernel<<<(int)(((long long)MTOK * DVAL + 255) / 256), 256>>>(ctxp, cls_token, pos_embed);

    const long long D2 = (long long)DVAL * DVAL;
    const long long DM = (long long)DVAL * MLPD;

    for (int L = 0; L < DEPTH; L++) {
        // LN1
        ln_kernel<<<MTOK, 256>>>(tokp, hp, ln1_w + L * DVAL, ln1_b + L * DVAL);
        // Q, K, V (tensor cores)
        launch_tf32(0, MTOK, DVAL, DVAL, hp, DVAL, wq + L * D2, DVAL, qp, DVAL, nullptr);
        launch_tf32(0, MTOK, DVAL, DVAL, hp, DVAL, wk + L * D2, DVAL, kp, DVAL, nullptr);
        launch_tf32(0, MTOK, DVAL, DVAL, hp, DVAL, wv + L * D2, DVAL, vp, DVAL, nullptr);
        // scores = Q @ K^T (fp32, batched over B*H)
        launch_gemm(0, 1, NTOK, NTOK, DKV,
                    qp, DVAL, (long long)NTOK * DVAL, DKV,
                    kp, DVAL, (long long)NTOK * DVAL, DKV,
                    scp, NTOK, (long long)HEADS * NNSC, NNSC,
                    nullptr, BVAL * HEADS, HEADS);
        softmax_kernel<<<(BVAL * HEADS * NTOK) / 8, 256>>>(scp);
        // ctx = attn @ V (fp32, batched)
        launch_gemm(0, 0, NTOK, DKV, NTOK,
                    scp, NTOK, (long long)HEADS * NNSC, NNSC,
                    vp, DVAL, (long long)NTOK * DVAL, DKV,
                    ctxp, DVAL, (long long)NTOK * DVAL, DKV,
                    nullptr, BVAL * HEADS, HEADS);
        // tok += ctx @ Wo + bo (tensor cores)
        launch_tf32(3, MTOK, DVAL, DVAL, ctxp, DVAL, wo_w + L * D2, DVAL, tokp, DVAL, wo_b + L * DVAL);
        // LN2
        ln_kernel<<<MTOK, 256>>>(tokp, hp, ln2_w + L * DVAL, ln2_b + L * DVAL);
        // hid = gelu(h @ W1 + b1) (tensor cores)
        launch_tf32(2, MTOK, MLPD, DVAL, hp, DVAL, mlp1_w + L * DM, MLPD, hidp, MLPD, mlp1_b + L * MLPD);
        // tok += hid @ W2 + b2 (tensor cores)
        launch_tf32(3, MTOK, DVAL, MLPD, hidp, MLPD, mlp2_w + L * DM, DVAL, tokp, DVAL, mlp2_b + L * DVAL);
    }

    head_kernel<<<BVAL, 256>>>(tokp, fnorm_w, fnorm_b, hln_w, hln_b,
                               h1_w, h1_b, h2_w, h2_b, (float*)d_out);
}

// round 4
// speedup vs baseline: 3.0681x; 1.0223x over previous
#include <cuda_runtime.h>
#include <cuda_fp16.h>
#include <math.h>
#include <stdint.h>

// ---------------- model constants ----------------
#define BVAL   32
#define DVAL   768
#define NTOK   197
#define NPATCH 196
#define HEADS  12
#define DKV    64
#define MLPD   3072
#define DEPTH  12
#define MTOK   (BVAL*NTOK)     // 6304
#define MPATCH (BVAL*NPATCH)   // 6272
#define NNSC   (NTOK*NTOK)     // 38809

// weight-plane offsets (halves)
#define SZ_ATT  (DEPTH*DVAL*DVAL)          // 7,077,888
#define SZ_MLP  (DEPTH*DVAL*MLPD)          // 28,311,552
#define OFF_WQ  0
#define OFF_WK  (SZ_ATT)
#define OFF_WV  (2*SZ_ATT)
#define OFF_WO  (3*SZ_ATT)
#define OFF_M1  (4*SZ_ATT)
#define OFF_M2  (4*SZ_ATT + SZ_MLP)
#define OFF_WT  (4*SZ_ATT + 2*SZ_MLP)
#define SZ_ALL  (OFF_WT + DVAL*DVAL)       // 85,524,480

// ---------------- scratch (static device globals; no allocation) ----------------
__device__ float g_tok[MTOK*DVAL];
__device__ float g_hbuf[MTOK*DVAL];
__device__ float g_q[MTOK*DVAL];
__device__ float g_k[MTOK*DVAL];
__device__ float g_v[MTOK*DVAL];
__device__ float g_ctx[MTOK*DVAL];
__device__ float g_scores[(long long)BVAL*HEADS*NNSC];
__device__ float g_hid[(long long)MTOK*MLPD];
__device__ float g_col[(long long)MPATCH*DVAL];
__device__ __half g_bh[SZ_ALL];
__device__ __half g_bl[SZ_ALL];

__device__ __forceinline__ float gelu_f(float x) {
    return 0.5f * x * (1.0f + erff(x * 0.70710678118654752440f));
}

__device__ __forceinline__ void split2(float x, __half& h, __half& l) {
    h = __float2half_rn(x);
    l = __float2half_rn(x - __half2float(h));
}

__device__ __forceinline__ uint32_t smem_u32(const void* p) {
    return (uint32_t)__cvta_generic_to_shared(p);
}

__device__ __forceinline__ void ldsm_x4(uint32_t* r, uint32_t addr) {
    asm volatile("ldmatrix.sync.aligned.m8n8.x4.shared.b16 {%0,%1,%2,%3}, [%4];"
                 : "=r"(r[0]), "=r"(r[1]), "=r"(r[2]), "=r"(r[3]) : "r"(addr));
}
__device__ __forceinline__ void ldsm_x4_t(uint32_t* r, uint32_t addr) {
    asm volatile("ldmatrix.sync.aligned.m8n8.x4.trans.shared.b16 {%0,%1,%2,%3}, [%4];"
                 : "=r"(r[0]), "=r"(r[1]), "=r"(r[2]), "=r"(r[3]) : "r"(addr));
}
__device__ __forceinline__ void mma16816(float* c, const uint32_t* a, const uint32_t* b) {
    asm volatile("mma.sync.aligned.m16n8k16.row.col.f32.f16.f16.f32 "
                 "{%0,%1,%2,%3},{%4,%5,%6,%7},{%8,%9},{%0,%1,%2,%3};"
                 : "+f"(c[0]), "+f"(c[1]), "+f"(c[2]), "+f"(c[3])
                 : "r"(a[0]), "r"(a[1]), "r"(a[2]), "r"(a[3]), "r"(b[0]), "r"(b[1]));
}

// =========================================================================
// fp16-split (3-term) tensor-core GEMM: C[M,N] = epi(A[M,K] @ B[K,N])
// A: fp32, split in-kernel. B: pre-split half planes Bh/Bl, layout [K,N].
// K % 16 == 0, N % 128 == 0; M bounds-checked.
// Block 128x128, 8 warps (64x32 each), double-buffered smem, ldmatrix.
// EPI: 0 = store ; 2 = store gelu(acc+bias) ; 3 = C += acc+bias
// =========================================================================
#define ASTR 24    // halves per A row (16 + 8 pad) -> conflict-free ldmatrix
#define BSTR 136   // halves per B k-row (128 + 8 pad)

template<int EPI>
__global__ __launch_bounds__(256)
void hsgemm_kernel(int M, int N, int K,
                   const float* __restrict__ A, int lda,
                   const __half* __restrict__ Bh, const __half* __restrict__ Bl, int ldb,
                   float* __restrict__ C, int ldc,
                   const float* __restrict__ bias)
{
    __shared__ __align__(16) __half As[2][2][128 * ASTR];
    __shared__ __align__(16) __half Bs[2][2][16 * BSTR];

    const int tid = threadIdx.x;
    const int lane = tid & 31, wid = tid >> 5;
    const int warpM = wid >> 2, warpN = wid & 3;
    const int quad = lane & 3, gid = lane >> 2;
    const int row0 = blockIdx.y * 128, col0 = blockIdx.x * 128;

    float acc[4][4][4];
    #pragma unroll
    for (int i = 0; i < 4; i++)
        #pragma unroll
        for (int j = 0; j < 4; j++)
            #pragma unroll
            for (int r = 0; r < 4; r++) acc[i][j][r] = 0.f;

    // A-tile staging coords: 128 rows x 16 k fp32, 2 float4 per thread
    int aR[2], aC[2];
    #pragma unroll
    for (int i = 0; i < 2; i++) {
        int e = tid + i * 256;
        aR[i] = e >> 2;  aC[i] = (e & 3) * 4;
    }
    // B-tile staging coords: 16 k-rows x 128 n halves per plane, 1 uint4/plane/thread
    const int bRr = (tid >> 4) & 15;
    const int bCc = tid & 15;

    const int nk = K / 16;
    float4 va[2];
    uint4 vbh, vbl;

    // ---- stage tile 0 ----
    #pragma unroll
    for (int i = 0; i < 2; i++) {
        int gm = row0 + aR[i];
        va[i] = (gm < M) ? *(const float4*)(A + (size_t)gm * lda + aC[i])
                         : make_float4(0.f, 0.f, 0.f, 0.f);
    }
    vbh = *(const uint4*)(Bh + (size_t)bRr * ldb + col0 + bCc * 8);
    vbl = *(const uint4*)(Bl + (size_t)bRr * ldb + col0 + bCc * 8);
    {
        #pragma unroll
        for (int i = 0; i < 2; i++) {
            __half h0,h1,h2,h3,l0,l1,l2,l3;
            split2(va[i].x,h0,l0); split2(va[i].y,h1,l1);
            split2(va[i].z,h2,l2); split2(va[i].w,h3,l3);
            __half2* ph = (__half2*)&As[0][0][aR[i]*ASTR + aC[i]];
            ph[0] = __halves2half2(h0,h1); ph[1] = __halves2half2(h2,h3);
            __half2* pl = (__half2*)&As[0][1][aR[i]*ASTR + aC[i]];
            pl[0] = __halves2half2(l0,l1); pl[1] = __halves2half2(l2,l3);
        }
        *(uint4*)&Bs[0][0][bRr*BSTR + bCc*8] = vbh;
        *(uint4*)&Bs[0][1][bRr*BSTR + bCc*8] = vbl;
    }
    __syncthreads();

    for (int kt = 0; kt < nk; kt++) {
        const int cur = kt & 1;
        const bool more = (kt + 1 < nk);
        if (more) {
            int k0 = (kt + 1) * 16;
            #pragma unroll
            for (int i = 0; i < 2; i++) {
                int gm = row0 + aR[i];
                va[i] = (gm < M) ? *(const float4*)(A + (size_t)gm * lda + k0 + aC[i])
                                 : make_float4(0.f, 0.f, 0.f, 0.f);
            }
            vbh = *(const uint4*)(Bh + (size_t)(k0 + bRr) * ldb + col0 + bCc * 8);
            vbl = *(const uint4*)(Bl + (size_t)(k0 + bRr) * ldb + col0 + bCc * 8);
        }

        // ---- fragments + mma on buffer cur ----
        {
            uint32_t ah[4][4], al[4][4], bh[4][2], bl[4][2];
            const uint32_t aoff = (uint32_t)((((lane & 15)) * ASTR + (lane >> 4) * 8) * 2);
            const uint32_t ah_base = smem_u32(&As[cur][0][0]) + aoff;
            const uint32_t al_base = smem_u32(&As[cur][1][0]) + aoff;
            #pragma unroll
            for (int mi = 0; mi < 4; mi++) {
                uint32_t o = (uint32_t)((warpM * 64 + mi * 16) * ASTR * 2);
                ldsm_x4(ah[mi], ah_base + o);
                ldsm_x4(al[mi], al_base + o);
            }
            const uint32_t boff = (uint32_t)(((lane & 15) * BSTR + (lane >> 4) * 8) * 2);
            const uint32_t bh_base = smem_u32(&Bs[cur][0][0]) + boff;
            const uint32_t bl_base = smem_u32(&Bs[cur][1][0]) + boff;
            #pragma unroll
            for (int np = 0; np < 2; np++) {
                uint32_t o = (uint32_t)((warpN * 32 + np * 16) * 2);
                uint32_t r[4];
                ldsm_x4_t(r, bh_base + o);
                bh[np*2][0] = r[0]; bh[np*2][1] = r[1];
                bh[np*2+1][0] = r[2]; bh[np*2+1][1] = r[3];
                ldsm_x4_t(r, bl_base + o);
                bl[np*2][0] = r[0]; bl[np*2][1] = r[1];
                bl[np*2+1][0] = r[2]; bl[np*2+1][1] = r[3];
            }
            #pragma unroll
            for (int mi = 0; mi < 4; mi++)
                #pragma unroll
                for (int ni = 0; ni < 4; ni++) {
                    mma16816(acc[mi][ni], ah[mi], bh[ni]);
                    mma16816(acc[mi][ni], ah[mi], bl[ni]);
                    mma16816(acc[mi][ni], al[mi], bh[ni]);
                }
        }

        if (more) {
            const int nxt = cur ^ 1;
            #pragma unroll
            for (int i = 0; i < 2; i++) {
                __half h0,h1,h2,h3,l0,l1,l2,l3;
                split2(va[i].x,h0,l0); split2(va[i].y,h1,l1);
                split2(va[i].z,h2,l2); split2(va[i].w,h3,l3);
                __half2* ph = (__half2*)&As[nxt][0][aR[i]*ASTR + aC[i]];
                ph[0] = __halves2half2(h0,h1); ph[1] = __halves2half2(h2,h3);
                __half2* pl = (__half2*)&As[nxt][1][aR[i]*ASTR + aC[i]];
                pl[0] = __halves2half2(l0,l1); pl[1] = __halves2half2(l2,l3);
            }
            *(uint4*)&Bs[nxt][0][bRr*BSTR + bCc*8] = vbh;
            *(uint4*)&Bs[nxt][1][bRr*BSTR + bCc*8] = vbl;
            __syncthreads();
        }
    }

    // ---- epilogue ----
    #pragma unroll
    for (int mi = 0; mi < 4; mi++) {
        int r0 = row0 + warpM * 64 + mi * 16 + gid;
        int r1 = r0 + 8;
        #pragma unroll
        for (int ni = 0; ni < 4; ni++) {
            int c = col0 + warpN * 32 + ni * 8 + 2 * quad;
            float b0 = 0.f, b1 = 0.f;
            if (EPI >= 2) { b0 = bias[c]; b1 = bias[c + 1]; }
            if (r0 < M) {
                float x0 = acc[mi][ni][0] + b0, x1 = acc[mi][ni][1] + b1;
                if (EPI == 2) { x0 = gelu_f(x0); x1 = gelu_f(x1); }
                size_t idx = (size_t)r0 * ldc + c;
                if (EPI == 3) { C[idx] += x0; C[idx + 1] += x1; }
                else          { C[idx] = x0;  C[idx + 1] = x1; }
            }
            if (r1 < M) {
                float x0 = acc[mi][ni][2] + b0, x1 = acc[mi][ni][3] + b1;
                if (EPI == 2) { x0 = gelu_f(x0); x1 = gelu_f(x1); }
                size_t idx = (size_t)r1 * ldc + c;
                if (EPI == 3) { C[idx] += x0; C[idx + 1] += x1; }
                else          { C[idx] = x0;  C[idx + 1] = x1; }
            }
        }
    }
}

static void launch_hs(int epi, int M, int N, int K,
                      const float* A, int lda,
                      const __half* Bh, const __half* Bl, int ldb,
                      float* C, int ldc, const float* bias)
{
    dim3 grid(N / 128, (M + 127) / 128), blk(256);
    if      (epi == 0) hsgemm_kernel<0><<<grid, blk>>>(M, N, K, A, lda, Bh, Bl, ldb, C, ldc, bias);
    else if (epi == 2) hsgemm_kernel<2><<<grid, blk>>>(M, N, K, A, lda, Bh, Bl, ldb, C, ldc, bias);
    else               hsgemm_kernel<3><<<grid, blk>>>(M, N, K, A, lda, Bh, Bl, ldb, C, ldc, bias);
}

// ---------------- weight split conversion ----------------
__global__ void split_kernel(const float* __restrict__ s, __half* __restrict__ dh,
                             __half* __restrict__ dl, int n4)
{
    int i = blockIdx.x * 256 + threadIdx.x;
    if (i >= n4) return;
    float4 v = ((const float4*)s)[i];
    __half h0,h1,h2,h3,l0,l1,l2,l3;
    split2(v.x,h0,l0); split2(v.y,h1,l1); split2(v.z,h2,l2); split2(v.w,h3,l3);
    ((__half2*)dh)[2*i]   = __halves2half2(h0,h1);
    ((__half2*)dh)[2*i+1] = __halves2half2(h2,h3);
    ((__half2*)dl)[2*i]   = __halves2half2(l0,l1);
    ((__half2*)dl)[2*i+1] = __halves2half2(l2,l3);
}

// conv weight: [768 out][768 in] -> wT[k][n] split planes
__global__ void tconv_kernel(const float* __restrict__ w, __half* __restrict__ dh,
                             __half* __restrict__ dl)
{
    int idx = blockIdx.x * 256 + threadIdx.x;
    if (idx >= DVAL * DVAL) return;
    int k = idx / DVAL, n = idx % DVAL;
    float x = w[n * DVAL + k];
    __half h, l; split2(x, h, l);
    dh[idx] = h; dl[idx] = l;
}

// ---------------- batched fp32 SGEMM (attention score / ctx) ----------------
template<int EPI, int TRANSB>
__global__ __launch_bounds__(256)
void sgemm_kernel(int M, int N, int K,
                  const float* __restrict__ A, int lda, long long sA0, long long sA1,
                  const float* __restrict__ Bm, int ldb, long long sB0, long long sB1,
                  float* __restrict__ C, int ldc, long long sC0, long long sC1,
                  const float* __restrict__ bias, int hdiv)
{
    __shared__ float As[16][132];
    __shared__ float Bs[16][132];

    int z  = blockIdx.z;
    int zb = z / hdiv, zh = z - zb * hdiv;
    A  += zb * sA0 + zh * sA1;
    Bm += zb * sB0 + zh * sB1;
    C  += zb * sC0 + zh * sC1;

    int tid = threadIdx.x;
    int tx = tid & 15, ty = tid >> 4;
    int row0 = blockIdx.y * 128, col0 = blockIdx.x * 128;

    float acc[8][8];
    #pragma unroll
    for (int i = 0; i < 8; i++)
        #pragma unroll
        for (int j = 0; j < 8; j++) acc[i][j] = 0.f;

    for (int k0 = 0; k0 < K; k0 += 16) {
        #pragma unroll
        for (int i = 0; i < 8; i++) {
            int e = tid + i * 256;
            int m = e >> 4, kk = e & 15;
            int gm = row0 + m, gk = k0 + kk;
            float v = 0.f;
            if (gm < M && gk < K) v = A[(long long)gm * lda + gk];
            As[kk][m] = v;
        }
        #pragma unroll
        for (int i = 0; i < 8; i++) {
            int e = tid + i * 256;
            if (TRANSB) {
                int n = e >> 4, kk = e & 15;
                int gn = col0 + n, gk = k0 + kk;
                float v = 0.f;
                if (gn < N && gk < K) v = Bm[(long long)gn * ldb + gk];
                Bs[kk][n] = v;
            } else {
                int n = e & 127, kk = e >> 7;
                int gn = col0 + n, gk = k0 + kk;
                float v = 0.f;
                if (gn < N && gk < K) v = Bm[(long long)gk * ldb + gn];
                Bs[kk][n] = v;
            }
        }
        __syncthreads();

        #pragma unroll
        for (int kk = 0; kk < 16; kk++) {
            float a[8], b[8];
            #pragma unroll
            for (int i = 0; i < 8; i++) a[i] = As[kk][ty * 8 + i];
            #pragma unroll
            for (int j = 0; j < 8; j++) b[j] = Bs[kk][tx * 8 + j];
            #pragma unroll
            for (int i = 0; i < 8; i++)
                #pragma unroll
                for (int j = 0; j < 8; j++)
                    acc[i][j] = fmaf(a[i], b[j], acc[i][j]);
        }
        __syncthreads();
    }

    #pragma unroll
    for (int i = 0; i < 8; i++) {
        int gm = row0 + ty * 8 + i;
        if (gm >= M) continue;
        #pragma unroll
        for (int j = 0; j < 8; j++) {
            int gn = col0 + tx * 8 + j;
            if (gn >= N) continue;
            float r = acc[i][j];
            if (EPI >= 1) r += bias[gn];
            long long idx = (long long)gm * ldc + gn;
            if (EPI == 3) C[idx] += r;
            else          C[idx] = r;
        }
    }
}

// ---------------- LayerNorm ----------------
__global__ void ln_kernel(const float* __restrict__ in, float* __restrict__ out,
                          const float* __restrict__ w, const float* __restrict__ b)
{
    __shared__ float red[256];
    int row = blockIdx.x;
    int tid = threadIdx.x;
    const float* x = in + (long long)row * DVAL;

    float v0 = x[tid], v1 = x[tid + 256], v2 = x[tid + 512];
    red[tid] = v0 + v1 + v2;
    __syncthreads();
    for (int o = 128; o > 0; o >>= 1) { if (tid < o) red[tid] += red[tid + o]; __syncthreads(); }
    float mu = red[0] * (1.0f / 768.0f);
    __syncthreads();

    float d0 = v0 - mu, d1 = v1 - mu, d2 = v2 - mu;
    red[tid] = d0 * d0 + d1 * d1 + d2 * d2;
    __syncthreads();
    for (int o = 128; o > 0; o >>= 1) { if (tid < o) red[tid] += red[tid + o]; __syncthreads(); }
    float rs = rsqrtf(red[0] * (1.0f / 768.0f) + 1e-5f);

    float* y = out + (long long)row * DVAL;
    y[tid]       = d0 * rs * w[tid]       + b[tid];
    y[tid + 256] = d1 * rs * w[tid + 256] + b[tid + 256];
    y[tid + 512] = d2 * rs * w[tid + 512] + b[tid + 512];
}

// ---------------- softmax (197), warp per row; scale folded in ----------------
__global__ void softmax_kernel(float* __restrict__ s)
{
    int row = blockIdx.x * 8 + (threadIdx.x >> 5);
    if (row >= BVAL * HEADS * NTOK) return;
    int lane = threadIdx.x & 31;
    float* p = s + (long long)row * NTOK;
    const float scale = 0.125f;

    float vals[7];
    float mx = -1e30f;
    #pragma unroll
    for (int i = 0; i < 7; i++) {
        int c = lane + i * 32;
        float v = (c < NTOK) ? p[c] * scale : -1e30f;
        vals[i] = v;
        mx = fmaxf(mx, v);
    }
    #pragma unroll
    for (int o = 16; o > 0; o >>= 1) mx = fmaxf(mx, __shfl_xor_sync(0xffffffffu, mx, o));

    float sum = 0.f;
    #pragma unroll
    for (int i = 0; i < 7; i++) {
        int c = lane + i * 32;
        float e = (c < NTOK) ? expf(vals[i] - mx) : 0.f;
        vals[i] = e;
        sum += e;
    }
    #pragma unroll
    for (int o = 16; o > 0; o >>= 1) sum += __shfl_xor_sync(0xffffffffu, sum, o);
    float inv = 1.0f / sum;

    #pragma unroll
    for (int i = 0; i < 7; i++) {
        int c = lane + i * 32;
        if (c < NTOK) p[c] = vals[i] * inv;
    }
}

// ---------------- patch-embed helpers ----------------
__global__ void im2col_kernel(const float* __restrict__ x)
{
    long long idx = (long long)blockIdx.x * blockDim.x + threadIdx.x;
    if (idx >= (long long)MPATCH * DVAL) return;
    int col = (int)(idx % DVAL);
    long long r = idx / DVAL;
    int p = (int)(r % NPATCH);
    int b = (int)(r / NPATCH);
    int c = col >> 8;
    int rem = col & 255;
    int i = rem >> 4, j = rem & 15;
    int py = p / 14, px = p % 14;
    g_col[idx] = x[(((long long)b * 3 + c) * 224 + py * 16 + i) * 224 + px * 16 + j];
}

__global__ void assemble_tok_kernel(const float* __restrict__ patch,
                                    const float* __restrict__ cls,
                                    const float* __restrict__ pos)
{
    long long idx = (long long)blockIdx.x * blockDim.x + threadIdx.x;
    if (idx >= (long long)MTOK * DVAL) return;
    int d = (int)(idx % DVAL);
    long long r = idx / DVAL;
    int n = (int)(r % NTOK);
    int b = (int)(r / NTOK);
    float v;
    if (n == 0) v = cls[d];
    else        v = patch[((long long)b * NPATCH + (n - 1)) * DVAL + d];
    g_tok[idx] = v + pos[n * DVAL + d];
}

// ---------------- head ----------------
__global__ void head_kernel(const float* __restrict__ tok,
                            const float* __restrict__ fw, const float* __restrict__ fb,
                            const float* __restrict__ hw, const float* __restrict__ hb,
                            const float* __restrict__ h1w, const float* __restrict__ h1b,
                            const float* __restrict__ h2w, const float* __restrict__ h2b,
                            float* __restrict__ out)
{
    __shared__ float cbuf[DVAL];
    __shared__ float hid[MLPD];
    __shared__ float red[256];
    int b = blockIdx.x, tid = threadIdx.x;
    const float* t = tok + (long long)b * NTOK * DVAL;

    float v0 = t[tid], v1 = t[tid + 256], v2 = t[tid + 512];
    red[tid] = v0 + v1 + v2; __syncthreads();
    for (int o = 128; o > 0; o >>= 1) { if (tid < o) red[tid] += red[tid + o]; __syncthreads(); }
    float mu = red[0] * (1.0f / 768.0f); __syncthreads();
    float d0 = v0 - mu, d1 = v1 - mu, d2 = v2 - mu;
    red[tid] = d0 * d0 + d1 * d1 + d2 * d2; __syncthreads();
    for (int o = 128; o > 0; o >>= 1) { if (tid < o) red[tid] += red[tid + o]; __syncthreads(); }
    float rs = rsqrtf(red[0] * (1.0f / 768.0f) + 1e-5f); __syncthreads();
    float u0 = d0 * rs * fw[tid]       + fb[tid];
    float u1 = d1 * rs * fw[tid + 256] + fb[tid + 256];
    float u2 = d2 * rs * fw[tid + 512] + fb[tid + 512];

    red[tid] = u0 + u1 + u2; __syncthreads();
    for (int o = 128; o > 0; o >>= 1) { if (tid < o) red[tid] += red[tid + o]; __syncthreads(); }
    mu = red[0] * (1.0f / 768.0f); __syncthreads();
    d0 = u0 - mu; d1 = u1 - mu; d2 = u2 - mu;
    red[tid] = d0 * d0 + d1 * d1 + d2 * d2; __syncthreads();
    for (int o = 128; o > 0; o >>= 1) { if (tid < o) red[tid] += red[tid + o]; __syncthreads(); }
    rs = rsqrtf(red[0] * (1.0f / 768.0f) + 1e-5f); __syncthreads();
    cbuf[tid]       = d0 * rs * hw[tid]       + hb[tid];
    cbuf[tid + 256] = d1 * rs * hw[tid + 256] + hb[tid + 256];
    cbuf[tid + 512] = d2 * rs * hw[tid + 512] + hb[tid + 512];
    __syncthreads();

    for (int j = tid; j < MLPD; j += 256) {
        float sacc = h1b[j];
        for (int d = 0; d < DVAL; d++)
            sacc = fmaf(cbuf[d], h1w[(long long)d * MLPD + j], sacc);
        hid[j] = gelu_f(sacc);
    }
    __syncthreads();

    for (int c2 = 0; c2 < 2; c2++) {
        float part = 0.f;
        for (int j = tid; j < MLPD; j += 256)
            part = fmaf(hid[j], h2w[j * 2 + c2], part);
        red[tid] = part; __syncthreads();
        for (int o = 128; o > 0; o >>= 1) { if (tid < o) red[tid] += red[tid + o]; __syncthreads(); }
        if (tid == 0) out[b * 2 + c2] = red[0] + h2b[c2];
        __syncthreads();
    }
}

// ---------------- fp32 GEMM dispatch (attention) ----------------
static void launch_gemm(int epi, int transb, int M, int N, int K,
                        const float* A, int lda, long long sA0, long long sA1,
                        const float* Bm, int ldb, long long sB0, long long sB1,
                        float* C, int ldc, long long sC0, long long sC1,
                        const float* bias, int batch, int hdiv)
{
    dim3 grid((N + 127) / 128, (M + 127) / 128, batch), blk(256);
#define GEMM_CALL(E, T) sgemm_kernel<E, T><<<grid, blk>>>(M, N, K, A, lda, sA0, sA1, Bm, ldb, sB0, sB1, C, ldc, sC0, sC1, bias, hdiv)
    if (transb == 0) {
        if (epi == 0) GEMM_CALL(0, 0); else GEMM_CALL(3, 0);
    } else {
        if (epi == 0) GEMM_CALL(0, 1); else GEMM_CALL(3, 1);
    }
#undef GEMM_CALL
}

extern "C" void kernel_launch(void* const* d_in, const int* in_sizes, int n_in,
                              void* d_out, int out_size)
{
    const float* x         = (const float*)d_in[0];
    const float* conv_w    = (const float*)d_in[1];
    const float* conv_b    = (const float*)d_in[2];
    const float* cls_token = (const float*)d_in[3];
    const float* pos_embed = (const float*)d_in[4];
    const float* ln1_w     = (const float*)d_in[5];
    const float* ln1_b     = (const float*)d_in[6];
    const float* wq        = (const float*)d_in[7];
    const float* wk        = (const float*)d_in[8];
    const float* wv        = (const float*)d_in[9];
    const float* wo_w      = (const float*)d_in[10];
    const float* wo_b      = (const float*)d_in[11];
    const float* ln2_w     = (const float*)d_in[12];
    const float* ln2_b     = (const float*)d_in[13];
    const float* mlp1_w    = (const float*)d_in[14];
    const float* mlp1_b    = (const float*)d_in[15];
    const float* mlp2_w    = (const float*)d_in[16];
    const float* mlp2_b    = (const float*)d_in[17];
    const float* fnorm_w   = (const float*)d_in[18];
    const float* fnorm_b   = (const float*)d_in[19];
    const float* hln_w     = (const float*)d_in[20];
    const float* hln_b     = (const float*)d_in[21];
    const float* h1_w      = (const float*)d_in[22];
    const float* h1_b      = (const float*)d_in[23];
    const float* h2_w      = (const float*)d_in[24];
    const float* h2_b      = (const float*)d_in[25];

    float *tokp, *hp, *qp, *kp, *vp, *ctxp, *scp, *hidp, *colp;
    __half *bh, *bl;
    cudaGetSymbolAddress((void**)&tokp, g_tok);
    cudaGetSymbolAddress((void**)&hp,   g_hbuf);
    cudaGetSymbolAddress((void**)&qp,   g_q);
    cudaGetSymbolAddress((void**)&kp,   g_k);
    cudaGetSymbolAddress((void**)&vp,   g_v);
    cudaGetSymbolAddress((void**)&ctxp, g_ctx);
    cudaGetSymbolAddress((void**)&scp,  g_scores);
    cudaGetSymbolAddress((void**)&hidp, g_hid);
    cudaGetSymbolAddress((void**)&colp, g_col);
    cudaGetSymbolAddress((void**)&bh,   g_bh);
    cudaGetSymbolAddress((void**)&bl,   g_bl);

    // ---- weight split conversion (hi/lo half planes) ----
    split_kernel<<<(SZ_ATT/4 + 255)/256, 256>>>(wq,     bh + OFF_WQ, bl + OFF_WQ, SZ_ATT/4);
    split_kernel<<<(SZ_ATT/4 + 255)/256, 256>>>(wk,     bh + OFF_WK, bl + OFF_WK, SZ_ATT/4);
    split_kernel<<<(SZ_ATT/4 + 255)/256, 256>>>(wv,     bh + OFF_WV, bl + OFF_WV, SZ_ATT/4);
    split_kernel<<<(SZ_ATT/4 + 255)/256, 256>>>(wo_w,   bh + OFF_WO, bl + OFF_WO, SZ_ATT/4);
    split_kernel<<<(SZ_MLP/4 + 255)/256, 256>>>(mlp1_w, bh + OFF_M1, bl + OFF_M1, SZ_MLP/4);
    split_kernel<<<(SZ_MLP/4 + 255)/256, 256>>>(mlp2_w, bh + OFF_M2, bl + OFF_M2, SZ_MLP/4);
    tconv_kernel<<<(DVAL*DVAL + 255)/256, 256>>>(conv_w, bh + OFF_WT, bl + OFF_WT);

    // ---- patch embed ----
    im2col_kernel<<<(int)(((long long)MPATCH * DVAL + 255) / 256), 256>>>(x);
    launch_hs(2, MPATCH, DVAL, DVAL, colp, DVAL, bh + OFF_WT, bl + OFF_WT, DVAL, ctxp, DVAL, conv_b);
    assemble_tok_kernel<<<(int)(((long long)MTOK * DVAL + 255) / 256), 256>>>(ctxp, cls_token, pos_embed);

    const long long D2 = (long long)DVAL * DVAL;
    const long long DM = (long long)DVAL * MLPD;

    for (int L = 0; L < DEPTH; L++) {
        ln_kernel<<<MTOK, 256>>>(tokp, hp, ln1_w + L * DVAL, ln1_b + L * DVAL);
        launch_hs(0, MTOK, DVAL, DVAL, hp, DVAL, bh + OFF_WQ + L * D2, bl + OFF_WQ + L * D2, DVAL, qp, DVAL, nullptr);
        launch_hs(0, MTOK, DVAL, DVAL, hp, DVAL, bh + OFF_WK + L * D2, bl + OFF_WK + L * D2, DVAL, kp, DVAL, nullptr);
        launch_hs(0, MTOK, DVAL, DVAL, hp, DVAL, bh + OFF_WV + L * D2, bl + OFF_WV + L * D2, DVAL, vp, DVAL, nullptr);
        // scores = Q @ K^T (fp32 batched)
        launch_gemm(0, 1, NTOK, NTOK, DKV,
                    qp, DVAL, (long long)NTOK * DVAL, DKV,
                    kp, DVAL, (long long)NTOK * DVAL, DKV,
                    scp, NTOK, (long long)HEADS * NNSC, NNSC,
                    nullptr, BVAL * HEADS, HEADS);
        softmax_kernel<<<(BVAL * HEADS * NTOK) / 8, 256>>>(scp);
        // ctx = attn @ V (fp32 batched)
        launch_gemm(0, 0, NTOK, DKV, NTOK,
                    scp, NTOK, (long long)HEADS * NNSC, NNSC,
                    vp, DVAL, (long long)NTOK * DVAL, DKV,
                    ctxp, DVAL, (long long)NTOK * DVAL, DKV,
                    nullptr, BVAL * HEADS, HEADS);
        // tok += ctx @ Wo + bo
        launch_hs(3, MTOK, DVAL, DVAL, ctxp, DVAL, bh + OFF_WO + L * D2, bl + OFF_WO + L * D2, DVAL, tokp, DVAL, wo_b + L * DVAL);
        ln_kernel<<<MTOK, 256>>>(tokp, hp, ln2_w + L * DVAL, ln2_b + L * DVAL);
        // hid = gelu(h @ W1 + b1)
        launch_hs(2, MTOK, MLPD, DVAL, hp, DVAL, bh + OFF_M1 + L * DM, bl + OFF_M1 + L * DM, MLPD, hidp, MLPD, mlp1_b + L * MLPD);
        // tok += hid @ W2 + b2
        launch_hs(3, MTOK, DVAL, MLPD, hidp, MLPD, bh + OFF_M2 + L * DM, bl + OFF_M2 + L * DM, DVAL, tokp, DVAL, mlp2_b + L * DVAL);
    }

    head_kernel<<<BVAL, 256>>>(tokp, fnorm_w, fnorm_b, hln_w, hln_b,
                               h1_w, h1_b, h2_w, h2_b, (float*)d_out);
}

// round 5
// speedup vs baseline: 3.9548x; 1.2890x over previous
#include <cuda_runtime.h>
#include <cuda_fp16.h>
#include <math.h>
#include <stdint.h>

// ---------------- model constants ----------------
#define BVAL   32
#define DVAL   768
#define NTOK   197
#define NPATCH 196
#define HEADS  12
#define DKV    64
#define MLPD   3072
#define DEPTH  12
#define MTOK   (BVAL*NTOK)     // 6304
#define MPATCH (BVAL*NPATCH)   // 6272
#define NNSC   (NTOK*NTOK)     // 38809
#define QKVN   (3*DVAL)        // 2304

// weight-plane offsets (in halves)
#define SZ_ATT  (DEPTH*DVAL*DVAL)          // 7,077,888
#define SZ_MLP  (DEPTH*DVAL*MLPD)          // 28,311,552
#define OFF_QKV 0
#define OFF_WO  (3*SZ_ATT)
#define OFF_M1  (4*SZ_ATT)
#define OFF_M2  (4*SZ_ATT + SZ_MLP)
#define OFF_WT  (4*SZ_ATT + 2*SZ_MLP)
#define SZ_ALL  (OFF_WT + DVAL*DVAL)

// ---------------- scratch (static device globals; no allocation) ----------------
__device__ float g_tok[MTOK*DVAL];
__device__ float g_hbuf[MTOK*DVAL];
__device__ float g_qkv[(long long)MTOK*QKVN];
__device__ float g_ctx[MTOK*DVAL];
__device__ float g_scores[(long long)BVAL*HEADS*NNSC];
__device__ float g_hid[(long long)MTOK*MLPD];
__device__ float g_col[(long long)MPATCH*DVAL];
__device__ __half g_bh[SZ_ALL];
__device__ __half g_bl[SZ_ALL];

__device__ __forceinline__ float gelu_f(float x) {
    return 0.5f * x * (1.0f + erff(x * 0.70710678118654752440f));
}

__device__ __forceinline__ void split2(float x, __half& h, __half& l) {
    h = __float2half_rn(x);
    l = __float2half_rn(x - __half2float(h));
}

__device__ __forceinline__ uint32_t smem_u32(const void* p) {
    return (uint32_t)__cvta_generic_to_shared(p);
}

__device__ __forceinline__ void ldsm_x4(uint32_t* r, uint32_t addr) {
    asm volatile("ldmatrix.sync.aligned.m8n8.x4.shared.b16 {%0,%1,%2,%3}, [%4];"
                 : "=r"(r[0]), "=r"(r[1]), "=r"(r[2]), "=r"(r[3]) : "r"(addr));
}
__device__ __forceinline__ void ldsm_x4_t(uint32_t* r, uint32_t addr) {
    asm volatile("ldmatrix.sync.aligned.m8n8.x4.trans.shared.b16 {%0,%1,%2,%3}, [%4];"
                 : "=r"(r[0]), "=r"(r[1]), "=r"(r[2]), "=r"(r[3]) : "r"(addr));
}
__device__ __forceinline__ void mma16816(float* c, const uint32_t* a, const uint32_t* b) {
    asm volatile("mma.sync.aligned.m16n8k16.row.col.f32.f16.f16.f32 "
                 "{%0,%1,%2,%3},{%4,%5,%6,%7},{%8,%9},{%0,%1,%2,%3};"
                 : "+f"(c[0]), "+f"(c[1]), "+f"(c[2]), "+f"(c[3])
                 : "r"(a[0]), "r"(a[1]), "r"(a[2]), "r"(a[3]), "r"(b[0]), "r"(b[1]));
}

// =========================================================================
// fp16-split (3-term) tensor-core GEMM (main path, B pre-split)
// Block 128x128, 8 warps (64x32 each), double-buffered smem, ldmatrix.
// EPI: 0 = store ; 2 = store gelu(acc+bias) ; 3 = C += acc+bias
// =========================================================================
#define ASTR 24
#define BSTR 136

template<int EPI>
__global__ __launch_bounds__(256)
void hsgemm_kernel(int M, int N, int K,
                   const float* __restrict__ A, int lda,
                   const __half* __restrict__ Bh, const __half* __restrict__ Bl, int ldb,
                   float* __restrict__ C, int ldc,
                   const float* __restrict__ bias)
{
    __shared__ __align__(16) __half As[2][2][128 * ASTR];
    __shared__ __align__(16) __half Bs[2][2][16 * BSTR];

    const int tid = threadIdx.x;
    const int lane = tid & 31, wid = tid >> 5;
    const int warpM = wid >> 2, warpN = wid & 3;
    const int quad = lane & 3, gid = lane >> 2;
    const int row0 = blockIdx.y * 128, col0 = blockIdx.x * 128;

    float acc[4][4][4];
    #pragma unroll
    for (int i = 0; i < 4; i++)
        #pragma unroll
        for (int j = 0; j < 4; j++)
            #pragma unroll
            for (int r = 0; r < 4; r++) acc[i][j][r] = 0.f;

    int aR[2], aC[2];
    #pragma unroll
    for (int i = 0; i < 2; i++) {
        int e = tid + i * 256;
        aR[i] = e >> 2;  aC[i] = (e & 3) * 4;
    }
    const int bRr = (tid >> 4) & 15;
    const int bCc = tid & 15;

    const int nk = K / 16;
    float4 va[2];
    uint4 vbh, vbl;

    #pragma unroll
    for (int i = 0; i < 2; i++) {
        int gm = row0 + aR[i];
        va[i] = (gm < M) ? *(const float4*)(A + (size_t)gm * lda + aC[i])
                         : make_float4(0.f, 0.f, 0.f, 0.f);
    }
    vbh = *(const uint4*)(Bh + (size_t)bRr * ldb + col0 + bCc * 8);
    vbl = *(const uint4*)(Bl + (size_t)bRr * ldb + col0 + bCc * 8);
    {
        #pragma unroll
        for (int i = 0; i < 2; i++) {
            __half h0,h1,h2,h3,l0,l1,l2,l3;
            split2(va[i].x,h0,l0); split2(va[i].y,h1,l1);
            split2(va[i].z,h2,l2); split2(va[i].w,h3,l3);
            __half2* ph = (__half2*)&As[0][0][aR[i]*ASTR + aC[i]];
            ph[0] = __halves2half2(h0,h1); ph[1] = __halves2half2(h2,h3);
            __half2* pl = (__half2*)&As[0][1][aR[i]*ASTR + aC[i]];
            pl[0] = __halves2half2(l0,l1); pl[1] = __halves2half2(l2,l3);
        }
        *(uint4*)&Bs[0][0][bRr*BSTR + bCc*8] = vbh;
        *(uint4*)&Bs[0][1][bRr*BSTR + bCc*8] = vbl;
    }
    __syncthreads();

    for (int kt = 0; kt < nk; kt++) {
        const int cur = kt & 1;
        const bool more = (kt + 1 < nk);
        if (more) {
            int k0 = (kt + 1) * 16;
            #pragma unroll
            for (int i = 0; i < 2; i++) {
                int gm = row0 + aR[i];
                va[i] = (gm < M) ? *(const float4*)(A + (size_t)gm * lda + k0 + aC[i])
                                 : make_float4(0.f, 0.f, 0.f, 0.f);
            }
            vbh = *(const uint4*)(Bh + (size_t)(k0 + bRr) * ldb + col0 + bCc * 8);
            vbl = *(const uint4*)(Bl + (size_t)(k0 + bRr) * ldb + col0 + bCc * 8);
        }

        {
            uint32_t ah[4][4], al[4][4], bh[4][2], bl[4][2];
            const uint32_t aoff = (uint32_t)((((lane & 15)) * ASTR + (lane >> 4) * 8) * 2);
            const uint32_t ah_base = smem_u32(&As[cur][0][0]) + aoff;
            const uint32_t al_base = smem_u32(&As[cur][1][0]) + aoff;
            #pragma unroll
            for (int mi = 0; mi < 4; mi++) {
                uint32_t o = (uint32_t)((warpM * 64 + mi * 16) * ASTR * 2);
                ldsm_x4(ah[mi], ah_base + o);
                ldsm_x4(al[mi], al_base + o);
            }
            const uint32_t boff = (uint32_t)(((lane & 15) * BSTR + (lane >> 4) * 8) * 2);
            const uint32_t bh_base = smem_u32(&Bs[cur][0][0]) + boff;
            const uint32_t bl_base = smem_u32(&Bs[cur][1][0]) + boff;
            #pragma unroll
            for (int np = 0; np < 2; np++) {
                uint32_t o = (uint32_t)((warpN * 32 + np * 16) * 2);
                uint32_t r[4];
                ldsm_x4_t(r, bh_base + o);
                bh[np*2][0] = r[0]; bh[np*2][1] = r[1];
                bh[np*2+1][0] = r[2]; bh[np*2+1][1] = r[3];
                ldsm_x4_t(r, bl_base + o);
                bl[np*2][0] = r[0]; bl[np*2][1] = r[1];
                bl[np*2+1][0] = r[2]; bl[np*2+1][1] = r[3];
            }
            #pragma unroll
            for (int mi = 0; mi < 4; mi++)
                #pragma unroll
                for (int ni = 0; ni < 4; ni++) {
                    mma16816(acc[mi][ni], ah[mi], bh[ni]);
                    mma16816(acc[mi][ni], ah[mi], bl[ni]);
                    mma16816(acc[mi][ni], al[mi], bh[ni]);
                }
        }

        if (more) {
            const int nxt = cur ^ 1;
            #pragma unroll
            for (int i = 0; i < 2; i++) {
                __half h0,h1,h2,h3,l0,l1,l2,l3;
                split2(va[i].x,h0,l0); split2(va[i].y,h1,l1);
                split2(va[i].z,h2,l2); split2(va[i].w,h3,l3);
                __half2* ph = (__half2*)&As[nxt][0][aR[i]*ASTR + aC[i]];
                ph[0] = __halves2half2(h0,h1); ph[1] = __halves2half2(h2,h3);
                __half2* pl = (__half2*)&As[nxt][1][aR[i]*ASTR + aC[i]];
                pl[0] = __halves2half2(l0,l1); pl[1] = __halves2half2(l2,l3);
            }
            *(uint4*)&Bs[nxt][0][bRr*BSTR + bCc*8] = vbh;
            *(uint4*)&Bs[nxt][1][bRr*BSTR + bCc*8] = vbl;
            __syncthreads();
        }
    }

    #pragma unroll
    for (int mi = 0; mi < 4; mi++) {
        int r0 = row0 + warpM * 64 + mi * 16 + gid;
        int r1 = r0 + 8;
        #pragma unroll
        for (int ni = 0; ni < 4; ni++) {
            int c = col0 + warpN * 32 + ni * 8 + 2 * quad;
            float b0 = 0.f, b1 = 0.f;
            if (EPI >= 2) { b0 = bias[c]; b1 = bias[c + 1]; }
            if (r0 < M) {
                float x0 = acc[mi][ni][0] + b0, x1 = acc[mi][ni][1] + b1;
                if (EPI == 2) { x0 = gelu_f(x0); x1 = gelu_f(x1); }
                size_t idx = (size_t)r0 * ldc + c;
                if (EPI == 3) { C[idx] += x0; C[idx + 1] += x1; }
                else          { C[idx] = x0;  C[idx + 1] = x1; }
            }
            if (r1 < M) {
                float x0 = acc[mi][ni][2] + b0, x1 = acc[mi][ni][3] + b1;
                if (EPI == 2) { x0 = gelu_f(x0); x1 = gelu_f(x1); }
                size_t idx = (size_t)r1 * ldc + c;
                if (EPI == 3) { C[idx] += x0; C[idx + 1] += x1; }
                else          { C[idx] = x0;  C[idx + 1] = x1; }
            }
        }
    }
}

static void launch_hs(int epi, int M, int N, int K,
                      const float* A, int lda,
                      const __half* Bh, const __half* Bl, int ldb,
                      float* C, int ldc, const float* bias)
{
    dim3 grid(N / 128, (M + 127) / 128), blk(256);
    if      (epi == 0) hsgemm_kernel<0><<<grid, blk>>>(M, N, K, A, lda, Bh, Bl, ldb, C, ldc, bias);
    else if (epi == 2) hsgemm_kernel<2><<<grid, blk>>>(M, N, K, A, lda, Bh, Bl, ldb, C, ldc, bias);
    else               hsgemm_kernel<3><<<grid, blk>>>(M, N, K, A, lda, Bh, Bl, ldb, C, ldc, bias);
}

// =========================================================================
// batched split-fp16 TC GEMM for attention. Tile 128(M) x 64(N), 8 warps 4x2,
// both operands fp32 split in-kernel, K bounds-padded (for K=197).
// TRANSB=1: B element [n,k] at B[n*ldb+k] (QK^T). TRANSB=0: B[k*ldb+n].
// =========================================================================
#define ASTR2 24
#define BSTR2 72

template<int TRANSB>
__global__ __launch_bounds__(256)
void attn_gemm(int M, int N, int K,
               const float* __restrict__ A, int lda, long long sA0, long long sA1,
               const float* __restrict__ B, int ldb, long long sB0, long long sB1,
               float* __restrict__ C, int ldc, long long sC0, long long sC1,
               int hdiv)
{
    __shared__ __align__(16) __half As[2][128 * ASTR2];
    __shared__ __align__(16) __half Bs[2][16 * BSTR2];

    const int z = blockIdx.z;
    const int zb = z / hdiv, zh = z - zb * hdiv;
    A += zb * sA0 + zh * sA1;
    B += zb * sB0 + zh * sB1;
    C += zb * sC0 + zh * sC1;

    const int tid = threadIdx.x;
    const int lane = tid & 31, wid = tid >> 5;
    const int warpM = wid >> 1, warpN = wid & 1;
    const int quad = lane & 3, gid = lane >> 2;
    const int row0 = blockIdx.y * 128, col0 = blockIdx.x * 64;

    float acc[2][4][4];
    #pragma unroll
    for (int i = 0; i < 2; i++)
        #pragma unroll
        for (int j = 0; j < 4; j++)
            #pragma unroll
            for (int r = 0; r < 4; r++) acc[i][j][r] = 0.f;

    const int nk = (K + 15) / 16;

    for (int kt = 0; kt < nk; kt++) {
        const int k0 = kt * 16;
        // ---- stage A tile: 128 rows x 16 k (scalar loads; lda may be odd) ----
        #pragma unroll
        for (int i = 0; i < 2; i++) {
            int e = tid + i * 256;
            int ar = e >> 2, ac = (e & 3) * 4;
            int gm = row0 + ar;
            #pragma unroll
            for (int j = 0; j < 4; j++) {
                int gk = k0 + ac + j;
                float v = (gm < M && gk < K) ? A[(size_t)gm * lda + gk] : 0.f;
                __half h, l; split2(v, h, l);
                As[0][ar * ASTR2 + ac + j] = h;
                As[1][ar * ASTR2 + ac + j] = l;
            }
        }
        // ---- stage B tile: 16 k x 64 n ----
        if (TRANSB) {
            int nloc = tid >> 2, kc = (tid & 3) * 4;
            int gn = col0 + nloc;
            #pragma unroll
            for (int j = 0; j < 4; j++) {
                int gk = k0 + kc + j;
                float v = (gn < N && gk < K) ? B[(size_t)gn * ldb + gk] : 0.f;
                __half h, l; split2(v, h, l);
                Bs[0][(kc + j) * BSTR2 + nloc] = h;
                Bs[1][(kc + j) * BSTR2 + nloc] = l;
            }
        } else {
            int kl = tid >> 4, nc = (tid & 15) * 4;
            int gk = k0 + kl;
            #pragma unroll
            for (int j = 0; j < 4; j++) {
                int gn = col0 + nc + j;
                float v = (gk < K && gn < N) ? B[(size_t)gk * ldb + gn] : 0.f;
                __half h, l; split2(v, h, l);
                Bs[0][kl * BSTR2 + nc + j] = h;
                Bs[1][kl * BSTR2 + nc + j] = l;
            }
        }
        __syncthreads();

        // ---- fragments + mma ----
        {
            uint32_t ah[2][4], al[2][4], bh[4][2], bl[4][2];
            const uint32_t aoff = (uint32_t)(((lane & 15) * ASTR2 + (lane >> 4) * 8) * 2);
            const uint32_t ah_base = smem_u32(&As[0][0]) + aoff;
            const uint32_t al_base = smem_u32(&As[1][0]) + aoff;
            #pragma unroll
            for (int mi = 0; mi < 2; mi++) {
                uint32_t o = (uint32_t)((warpM * 32 + mi * 16) * ASTR2 * 2);
                ldsm_x4(ah[mi], ah_base + o);
                ldsm_x4(al[mi], al_base + o);
            }
            const uint32_t boff = (uint32_t)(((lane & 15) * BSTR2 + (lane >> 4) * 8) * 2);
            const uint32_t bh_base = smem_u32(&Bs[0][0]) + boff;
            const uint32_t bl_base = smem_u32(&Bs[1][0]) + boff;
            #pragma unroll
            for (int np = 0; np < 2; np++) {
                uint32_t o = (uint32_t)((warpN * 32 + np * 16) * 2);
                uint32_t r[4];
                ldsm_x4_t(r, bh_base + o);
                bh[np*2][0] = r[0]; bh[np*2][1] = r[1];
                bh[np*2+1][0] = r[2]; bh[np*2+1][1] = r[3];
                ldsm_x4_t(r, bl_base + o);
                bl[np*2][0] = r[0]; bl[np*2][1] = r[1];
                bl[np*2+1][0] = r[2]; bl[np*2+1][1] = r[3];
            }
            #pragma unroll
            for (int mi = 0; mi < 2; mi++)
                #pragma unroll
                for (int ni = 0; ni < 4; ni++) {
                    mma16816(acc[mi][ni], ah[mi], bh[ni]);
                    mma16816(acc[mi][ni], ah[mi], bl[ni]);
                    mma16816(acc[mi][ni], al[mi], bh[ni]);
                }
        }
        __syncthreads();
    }

    // ---- epilogue (scalar, bounds on M and N) ----
    #pragma unroll
    for (int mi = 0; mi < 2; mi++) {
        int r0 = row0 + warpM * 32 + mi * 16 + gid;
        int r1 = r0 + 8;
        #pragma unroll
        for (int ni = 0; ni < 4; ni++) {
            int c = col0 + warpN * 32 + ni * 8 + 2 * quad;
            if (r0 < M) {
                if (c < N)     C[(size_t)r0 * ldc + c]     = acc[mi][ni][0];
                if (c + 1 < N) C[(size_t)r0 * ldc + c + 1] = acc[mi][ni][1];
            }
            if (r1 < M) {
                if (c < N)     C[(size_t)r1 * ldc + c]     = acc[mi][ni][2];
                if (c + 1 < N) C[(size_t)r1 * ldc + c + 1] = acc[mi][ni][3];
            }
        }
    }
}

// =========================================================================
// mega weight split: QKV packed [768,2304]/layer + wo + mlp1 + mlp2 + convT
// =========================================================================
__global__ void split_all_kernel(const float* __restrict__ wq, const float* __restrict__ wk,
                                 const float* __restrict__ wv, const float* __restrict__ wo,
                                 const float* __restrict__ m1, const float* __restrict__ m2,
                                 const float* __restrict__ cw,
                                 __half* __restrict__ bh, __half* __restrict__ bl)
{
    const long long QKV4 = 3LL * SZ_ATT / 4;
    const long long WO4  = (long long)SZ_ATT / 4;
    const long long M4   = (long long)SZ_MLP / 4;
    const long long TOT4 = QKV4 + WO4 + 2 * M4;

    long long i = (long long)blockIdx.x * 256 + threadIdx.x;

    if (i < QKV4) {
        int w = (int)(i / (SZ_ATT / 4));
        long long j = i - (long long)w * (SZ_ATT / 4);
        const float* src = (w == 0) ? wq : (w == 1) ? wk : wv;
        float4 v = ((const float4*)src)[j];
        long long s = 4 * j;
        int L = (int)(s / ((long long)DVAL * DVAL));
        int r = (int)(s - (long long)L * DVAL * DVAL);
        int k = r / DVAL, n = r - k * DVAL;
        long long d = OFF_QKV + (long long)L * DVAL * QKVN + (long long)k * QKVN + w * DVAL + n;
        __half h0,h1,h2,h3,l0,l1,l2,l3;
        split2(v.x,h0,l0); split2(v.y,h1,l1); split2(v.z,h2,l2); split2(v.w,h3,l3);
        __half2* ph = (__half2*)(bh + d);
        ph[0] = __halves2half2(h0,h1); ph[1] = __halves2half2(h2,h3);
        __half2* pl = (__half2*)(bl + d);
        pl[0] = __halves2half2(l0,l1); pl[1] = __halves2half2(l2,l3);
        return;
    }
    if (i < TOT4) {
        long long i2 = i - QKV4;
        const float* src; long long off, j;
        if (i2 < WO4)            { src = wo; off = OFF_WO; j = i2; }
        else if (i2 < WO4 + M4)  { src = m1; off = OFF_M1; j = i2 - WO4; }
        else                     { src = m2; off = OFF_M2; j = i2 - WO4 - M4; }
        float4 v = ((const float4*)src)[j];
        long long d = off + 4 * j;
        __half h0,h1,h2,h3,l0,l1,l2,l3;
        split2(v.x,h0,l0); split2(v.y,h1,l1); split2(v.z,h2,l2); split2(v.w,h3,l3);
        __half2* ph = (__half2*)(bh + d);
        ph[0] = __halves2half2(h0,h1); ph[1] = __halves2half2(h2,h3);
        __half2* pl = (__half2*)(bl + d);
        pl[0] = __halves2half2(l0,l1); pl[1] = __halves2half2(l2,l3);
        return;
    }
    long long idx = i - TOT4;
    if (idx < (long long)DVAL * DVAL) {
        int k = (int)(idx / DVAL), n = (int)(idx % DVAL);
        float x = cw[(long long)n * DVAL + k];
        __half h, l; split2(x, h, l);
        bh[OFF_WT + idx] = h;
        bl[OFF_WT + idx] = l;
    }
}

// ---------------- LayerNorm ----------------
__global__ void ln_kernel(const float* __restrict__ in, float* __restrict__ out,
                          const float* __restrict__ w, const float* __restrict__ b)
{
    __shared__ float red[256];
    int row = blockIdx.x;
    int tid = threadIdx.x;
    const float* x = in + (long long)row * DVAL;

    float v0 = x[tid], v1 = x[tid + 256], v2 = x[tid + 512];
    red[tid] = v0 + v1 + v2;
    __syncthreads();
    for (int o = 128; o > 0; o >>= 1) { if (tid < o) red[tid] += red[tid + o]; __syncthreads(); }
    float mu = red[0] * (1.0f / 768.0f);
    __syncthreads();

    float d0 = v0 - mu, d1 = v1 - mu, d2 = v2 - mu;
    red[tid] = d0 * d0 + d1 * d1 + d2 * d2;
    __syncthreads();
    for (int o = 128; o > 0; o >>= 1) { if (tid < o) red[tid] += red[tid + o]; __syncthreads(); }
    float rs = rsqrtf(red[0] * (1.0f / 768.0f) + 1e-5f);

    float* y = out + (long long)row * DVAL;
    y[tid]       = d0 * rs * w[tid]       + b[tid];
    y[tid + 256] = d1 * rs * w[tid + 256] + b[tid + 256];
    y[tid + 512] = d2 * rs * w[tid + 512] + b[tid + 512];
}

// ---------------- softmax (197), warp per row; scale folded in ----------------
__global__ void softmax_kernel(float* __restrict__ s)
{
    int row = blockIdx.x * 8 + (threadIdx.x >> 5);
    if (row >= BVAL * HEADS * NTOK) return;
    int lane = threadIdx.x & 31;
    float* p = s + (long long)row * NTOK;
    const float scale = 0.125f;

    float vals[7];
    float mx = -1e30f;
    #pragma unroll
    for (int i = 0; i < 7; i++) {
        int c = lane + i * 32;
        float v = (c < NTOK) ? p[c] * scale : -1e30f;
        vals[i] = v;
        mx = fmaxf(mx, v);
    }
    #pragma unroll
    for (int o = 16; o > 0; o >>= 1) mx = fmaxf(mx, __shfl_xor_sync(0xffffffffu, mx, o));

    float sum = 0.f;
    #pragma unroll
    for (int i = 0; i < 7; i++) {
        int c = lane + i * 32;
        float e = (c < NTOK) ? expf(vals[i] - mx) : 0.f;
        vals[i] = e;
        sum += e;
    }
    #pragma unroll
    for (int o = 16; o > 0; o >>= 1) sum += __shfl_xor_sync(0xffffffffu, sum, o);
    float inv = 1.0f / sum;

    #pragma unroll
    for (int i = 0; i < 7; i++) {
        int c = lane + i * 32;
        if (c < NTOK) p[c] = vals[i] * inv;
    }
}

// ---------------- patch-embed helpers ----------------
__global__ void im2col_kernel(const float* __restrict__ x)
{
    long long idx = (long long)blockIdx.x * blockDim.x + threadIdx.x;
    if (idx >= (long long)MPATCH * DVAL) return;
    int col = (int)(idx % DVAL);
    long long r = idx / DVAL;
    int p = (int)(r % NPATCH);
    int b = (int)(r / NPATCH);
    int c = col >> 8;
    int rem = col & 255;
    int i = rem >> 4, j = rem & 15;
    int py = p / 14, px = p % 14;
    g_col[idx] = x[(((long long)b * 3 + c) * 224 + py * 16 + i) * 224 + px * 16 + j];
}

__global__ void assemble_tok_kernel(const float* __restrict__ patch,
                                    const float* __restrict__ cls,
                                    const float* __restrict__ pos)
{
    long long idx = (long long)blockIdx.x * blockDim.x + threadIdx.x;
    if (idx >= (long long)MTOK * DVAL) return;
    int d = (int)(idx % DVAL);
    long long r = idx / DVAL;
    int n = (int)(r % NTOK);
    int b = (int)(r / NTOK);
    float v;
    if (n == 0) v = cls[d];
    else        v = patch[((long long)b * NPATCH + (n - 1)) * DVAL + d];
    g_tok[idx] = v + pos[n * DVAL + d];
}

// ---------------- head ----------------
__global__ void head_kernel(const float* __restrict__ tok,
                            const float* __restrict__ fw, const float* __restrict__ fb,
                            const float* __restrict__ hw, const float* __restrict__ hb,
                            const float* __restrict__ h1w, const float* __restrict__ h1b,
                            const float* __restrict__ h2w, const float* __restrict__ h2b,
                            float* __restrict__ out)
{
    __shared__ float cbuf[DVAL];
    __shared__ float hid[MLPD];
    __shared__ float red[256];
    int b = blockIdx.x, tid = threadIdx.x;
    const float* t = tok + (long long)b * NTOK * DVAL;

    float v0 = t[tid], v1 = t[tid + 256], v2 = t[tid + 512];
    red[tid] = v0 + v1 + v2; __syncthreads();
    for (int o = 128; o > 0; o >>= 1) { if (tid < o) red[tid] += red[tid + o]; __syncthreads(); }
    float mu = red[0] * (1.0f / 768.0f); __syncthreads();
    float d0 = v0 - mu, d1 = v1 - mu, d2 = v2 - mu;
    red[tid] = d0 * d0 + d1 * d1 + d2 * d2; __syncthreads();
    for (int o = 128; o > 0; o >>= 1) { if (tid < o) red[tid] += red[tid + o]; __syncthreads(); }
    float rs = rsqrtf(red[0] * (1.0f / 768.0f) + 1e-5f); __syncthreads();
    float u0 = d0 * rs * fw[tid]       + fb[tid];
    float u1 = d1 * rs * fw[tid + 256] + fb[tid + 256];
    float u2 = d2 * rs * fw[tid + 512] + fb[tid + 512];

    red[tid] = u0 + u1 + u2; __syncthreads();
    for (int o = 128; o > 0; o >>= 1) { if (tid < o) red[tid] += red[tid + o]; __syncthreads(); }
    mu = red[0] * (1.0f / 768.0f); __syncthreads();
    d0 = u0 - mu; d1 = u1 - mu; d2 = u2 - mu;
    red[tid] = d0 * d0 + d1 * d1 + d2 * d2; __syncthreads();
    for (int o = 128; o > 0; o >>= 1) { if (tid < o) red[tid] += red[tid + o]; __syncthreads(); }
    rs = rsqrtf(red[0] * (1.0f / 768.0f) + 1e-5f); __syncthreads();
    cbuf[tid]       = d0 * rs * hw[tid]       + hb[tid];
    cbuf[tid + 256] = d1 * rs * hw[tid + 256] + hb[tid + 256];
    cbuf[tid + 512] = d2 * rs * hw[tid + 512] + hb[tid + 512];
    __syncthreads();

    for (int j = tid; j < MLPD; j += 256) {
        float sacc = h1b[j];
        for (int d = 0; d < DVAL; d++)
            sacc = fmaf(cbuf[d], h1w[(long long)d * MLPD + j], sacc);
        hid[j] = gelu_f(sacc);
    }
    __syncthreads();

    for (int c2 = 0; c2 < 2; c2++) {
        float part = 0.f;
        for (int j = tid; j < MLPD; j += 256)
            part = fmaf(hid[j], h2w[j * 2 + c2], part);
        red[tid] = part; __syncthreads();
        for (int o = 128; o > 0; o >>= 1) { if (tid < o) red[tid] += red[tid + o]; __syncthreads(); }
        if (tid == 0) out[b * 2 + c2] = red[0] + h2b[c2];
        __syncthreads();
    }
}

extern "C" void kernel_launch(void* const* d_in, const int* in_sizes, int n_in,
                              void* d_out, int out_size)
{
    const float* x         = (const float*)d_in[0];
    const float* conv_w    = (const float*)d_in[1];
    const float* conv_b    = (const float*)d_in[2];
    const float* cls_token = (const float*)d_in[3];
    const float* pos_embed = (const float*)d_in[4];
    const float* ln1_w     = (const float*)d_in[5];
    const float* ln1_b     = (const float*)d_in[6];
    const float* wq        = (const float*)d_in[7];
    const float* wk        = (const float*)d_in[8];
    const float* wv        = (const float*)d_in[9];
    const float* wo_w      = (const float*)d_in[10];
    const float* wo_b      = (const float*)d_in[11];
    const float* ln2_w     = (const float*)d_in[12];
    const float* ln2_b     = (const float*)d_in[13];
    const float* mlp1_w    = (const float*)d_in[14];
    const float* mlp1_b    = (const float*)d_in[15];
    const float* mlp2_w    = (const float*)d_in[16];
    const float* mlp2_b    = (const float*)d_in[17];
    const float* fnorm_w   = (const float*)d_in[18];
    const float* fnorm_b   = (const float*)d_in[19];
    const float* hln_w     = (const float*)d_in[20];
    const float* hln_b     = (const float*)d_in[21];
    const float* h1_w      = (const float*)d_in[22];
    const float* h1_b      = (const float*)d_in[23];
    const float* h2_w      = (const float*)d_in[24];
    const float* h2_b      = (const float*)d_in[25];

    float *tokp, *hp, *qkvp, *ctxp, *scp, *hidp, *colp;
    __half *bh, *bl;
    cudaGetSymbolAddress((void**)&tokp, g_tok);
    cudaGetSymbolAddress((void**)&hp,   g_hbuf);
    cudaGetSymbolAddress((void**)&qkvp, g_qkv);
    cudaGetSymbolAddress((void**)&ctxp, g_ctx);
    cudaGetSymbolAddress((void**)&scp,  g_scores);
    cudaGetSymbolAddress((void**)&hidp, g_hid);
    cudaGetSymbolAddress((void**)&colp, g_col);
    cudaGetSymbolAddress((void**)&bh,   g_bh);
    cudaGetSymbolAddress((void**)&bl,   g_bl);

    // launch #0: single mega weight-split
    {
        long long tot = 3LL*SZ_ATT/4 + (long long)SZ_ATT/4 + 2LL*SZ_MLP/4 + (long long)DVAL*DVAL;
        int blocks = (int)((tot + 255) / 256);
        split_all_kernel<<<blocks, 256>>>(wq, wk, wv, wo_w, mlp1_w, mlp2_w, conv_w, bh, bl);
    }

    // #1 im2col, #2 patch GEMM, #3 assemble, #4 LN1(L0), #5 QKV GEMM(L0) <- ncu target
    im2col_kernel<<<(int)(((long long)MPATCH * DVAL + 255) / 256), 256>>>(x);
    launch_hs(2, MPATCH, DVAL, DVAL, colp, DVAL, bh + OFF_WT, bl + OFF_WT, DVAL, ctxp, DVAL, conv_b);
    assemble_tok_kernel<<<(int)(((long long)MTOK * DVAL + 255) / 256), 256>>>(ctxp, cls_token, pos_embed);

    const long long DQ = (long long)DVAL * QKVN;   // per-layer packed QKV plane
    const long long D2 = (long long)DVAL * DVAL;
    const long long DM = (long long)DVAL * MLPD;

    for (int L = 0; L < DEPTH; L++) {
        ln_kernel<<<MTOK, 256>>>(tokp, hp, ln1_w + L * DVAL, ln1_b + L * DVAL);
        // fused QKV GEMM: [6304, 2304]
        launch_hs(0, MTOK, QKVN, DVAL, hp, DVAL,
                  bh + OFF_QKV + L * DQ, bl + OFF_QKV + L * DQ, QKVN, qkvp, QKVN, nullptr);

        // scores = Q @ K^T (TC, batched over B*H)
        {
            dim3 grid((NTOK + 63) / 64, (NTOK + 127) / 128, BVAL * HEADS);
            attn_gemm<1><<<grid, 256>>>(NTOK, NTOK, DKV,
                qkvp,             QKVN, (long long)NTOK * QKVN, DKV,
                qkvp + DVAL,      QKVN, (long long)NTOK * QKVN, DKV,
                scp,              NTOK, (long long)HEADS * NNSC, NNSC,
                HEADS);
        }
        softmax_kernel<<<(BVAL * HEADS * NTOK) / 8, 256>>>(scp);
        // ctx = attn @ V (TC, batched)
        {
            dim3 grid(1, (NTOK + 127) / 128, BVAL * HEADS);
            attn_gemm<0><<<grid, 256>>>(NTOK, DKV, NTOK,
                scp,              NTOK, (long long)HEADS * NNSC, NNSC,
                qkvp + 2 * DVAL,  QKVN, (long long)NTOK * QKVN, DKV,
                ctxp,             DVAL, (long long)NTOK * DVAL, DKV,
                HEADS);
        }
        // tok += ctx @ Wo + bo
        launch_hs(3, MTOK, DVAL, DVAL, ctxp, DVAL,
                  bh + OFF_WO + L * D2, bl + OFF_WO + L * D2, DVAL, tokp, DVAL, wo_b + L * DVAL);
        ln_kernel<<<MTOK, 256>>>(tokp, hp, ln2_w + L * DVAL, ln2_b + L * DVAL);
        // hid = gelu(h @ W1 + b1)
        launch_hs(2, MTOK, MLPD, DVAL, hp, DVAL,
                  bh + OFF_M1 + L * DM, bl + OFF_M1 + L * DM, MLPD, hidp, MLPD, mlp1_b + L * MLPD);
        // tok += hid @ W2 + b2
        launch_hs(3, MTOK, DVAL, MLPD, hidp, MLPD,
                  bh + OFF_M2 + L * DM, bl + OFF_M2 + L * DM, DVAL, tokp, DVAL, mlp2_b + L * DVAL);
    }

    head_kernel<<<BVAL, 256>>>(tokp, fnorm_w, fnorm_b, hln_w, hln_b,
                               h1_w, h1_b, h2_w, h2_b, (float*)d_out);
}

// round 6
// speedup vs baseline: 4.0102x; 1.0140x over previous
#include <cuda_runtime.h>
#include <cuda_fp16.h>
#include <math.h>
#include <stdint.h>

// ---------------- model constants ----------------
#define BVAL   32
#define DVAL   768
#define NTOK   197
#define NPATCH 196
#define HEADS  12
#define DKV    64
#define MLPD   3072
#define DEPTH  12
#define MTOK   (BVAL*NTOK)     // 6304
#define MPATCH (BVAL*NPATCH)   // 6272
#define NNSC   (NTOK*NTOK)     // 38809
#define QKVN   (3*DVAL)        // 2304

// weight-plane offsets (in halves)
#define SZ_ATT  (DEPTH*DVAL*DVAL)
#define SZ_MLP  (DEPTH*DVAL*MLPD)
#define OFF_QKV 0
#define OFF_WO  (3*SZ_ATT)
#define OFF_M1  (4*SZ_ATT)
#define OFF_M2  (4*SZ_ATT + SZ_MLP)
#define OFF_WT  (4*SZ_ATT + 2*SZ_MLP)
#define SZ_ALL  (OFF_WT + DVAL*DVAL)

// ---------------- scratch ----------------
__device__ float g_tok[MTOK*DVAL];
__device__ float g_hbuf[MTOK*DVAL];
__device__ float g_qkv[(long long)MTOK*QKVN];
__device__ float g_ctx[MTOK*DVAL];
__device__ float g_scores[(long long)BVAL*HEADS*NNSC];
__device__ float g_hid[(long long)MTOK*MLPD];
__device__ float g_col[(long long)MPATCH*DVAL];
__device__ __half g_bh[SZ_ALL];
__device__ __half g_bl[SZ_ALL];

__device__ __forceinline__ float gelu_f(float x) {
    return 0.5f * x * (1.0f + erff(x * 0.70710678118654752440f));
}

__device__ __forceinline__ void split2(float x, __half& h, __half& l) {
    h = __float2half_rn(x);
    l = __float2half_rn(x - __half2float(h));
}

__device__ __forceinline__ uint32_t smem_u32(const void* p) {
    return (uint32_t)__cvta_generic_to_shared(p);
}

__device__ __forceinline__ void cp16(uint32_t dst, const void* src) {
    asm volatile("cp.async.cg.shared.global [%0], [%1], 16;" :: "r"(dst), "l"(src));
}
#define CP_COMMIT() asm volatile("cp.async.commit_group;")
#define CP_WAIT0()  asm volatile("cp.async.wait_group 0;")

__device__ __forceinline__ void ldsm_x4(uint32_t* r, uint32_t addr) {
    asm volatile("ldmatrix.sync.aligned.m8n8.x4.shared.b16 {%0,%1,%2,%3}, [%4];"
                 : "=r"(r[0]), "=r"(r[1]), "=r"(r[2]), "=r"(r[3]) : "r"(addr));
}
__device__ __forceinline__ void ldsm_x4_t(uint32_t* r, uint32_t addr) {
    asm volatile("ldmatrix.sync.aligned.m8n8.x4.trans.shared.b16 {%0,%1,%2,%3}, [%4];"
                 : "=r"(r[0]), "=r"(r[1]), "=r"(r[2]), "=r"(r[3]) : "r"(addr));
}
__device__ __forceinline__ void mma16816(float* c, const uint32_t* a, const uint32_t* b) {
    asm volatile("mma.sync.aligned.m16n8k16.row.col.f32.f16.f16.f32 "
                 "{%0,%1,%2,%3},{%4,%5,%6,%7},{%8,%9},{%0,%1,%2,%3};"
                 : "+f"(c[0]), "+f"(c[1]), "+f"(c[2]), "+f"(c[3])
                 : "r"(a[0]), "r"(a[1]), "r"(a[2]), "r"(a[3]), "r"(b[0]), "r"(b[1]));
}

// =========================================================================
// fp16-split (3-term) tensor-core GEMM (main path, B pre-split)
// Block 128x128, 8 warps (64x32 each), double-buffered smem, ldmatrix,
// cp.async for B planes. EPI: 0=store; 2=gelu(acc+bias); 3=C+=acc+bias
// =========================================================================
#define ASTR 24
#define BSTR 136

template<int EPI>
__global__ __launch_bounds__(256, 2)
void hsgemm_kernel(int M, int N, int K,
                   const float* __restrict__ A, int lda,
                   const __half* __restrict__ Bh, const __half* __restrict__ Bl, int ldb,
                   float* __restrict__ C, int ldc,
                   const float* __restrict__ bias)
{
    __shared__ __align__(16) __half As[2][2][128 * ASTR];
    __shared__ __align__(16) __half Bs[2][2][16 * BSTR];

    const int tid = threadIdx.x;
    const int lane = tid & 31, wid = tid >> 5;
    const int warpM = wid >> 2, warpN = wid & 3;
    const int quad = lane & 3, gid = lane >> 2;
    const int row0 = blockIdx.y * 128, col0 = blockIdx.x * 128;

    float acc[4][4][4];
    #pragma unroll
    for (int i = 0; i < 4; i++)
        #pragma unroll
        for (int j = 0; j < 4; j++)
            #pragma unroll
            for (int r = 0; r < 4; r++) acc[i][j][r] = 0.f;

    int aR[2], aC[2];
    #pragma unroll
    for (int i = 0; i < 2; i++) {
        int e = tid + i * 256;
        aR[i] = e >> 2;  aC[i] = (e & 3) * 4;
    }
    const int bRr = (tid >> 4) & 15;
    const int bCc = tid & 15;

    // B cp.async pointers
    const __half* bsrc_h = Bh + (size_t)bRr * ldb + col0 + bCc * 8;
    const __half* bsrc_l = Bl + (size_t)bRr * ldb + col0 + bCc * 8;
    uint32_t bdst_h[2], bdst_l[2];
    bdst_h[0] = smem_u32(&Bs[0][0][bRr*BSTR + bCc*8]);
    bdst_l[0] = smem_u32(&Bs[0][1][bRr*BSTR + bCc*8]);
    bdst_h[1] = smem_u32(&Bs[1][0][bRr*BSTR + bCc*8]);
    bdst_l[1] = smem_u32(&Bs[1][1][bRr*BSTR + bCc*8]);

    const int nk = K / 16;
    float4 va[2];

    // ---- prologue: stage tile 0 ----
    cp16(bdst_h[0], bsrc_h);
    cp16(bdst_l[0], bsrc_l);
    CP_COMMIT();
    #pragma unroll
    for (int i = 0; i < 2; i++) {
        int gm = row0 + aR[i];
        va[i] = (gm < M) ? *(const float4*)(A + (size_t)gm * lda + aC[i])
                         : make_float4(0.f, 0.f, 0.f, 0.f);
    }
    #pragma unroll
    for (int i = 0; i < 2; i++) {
        __half h0,h1,h2,h3,l0,l1,l2,l3;
        split2(va[i].x,h0,l0); split2(va[i].y,h1,l1);
        split2(va[i].z,h2,l2); split2(va[i].w,h3,l3);
        __half2* ph = (__half2*)&As[0][0][aR[i]*ASTR + aC[i]];
        ph[0] = __halves2half2(h0,h1); ph[1] = __halves2half2(h2,h3);
        __half2* pl = (__half2*)&As[0][1][aR[i]*ASTR + aC[i]];
        pl[0] = __halves2half2(l0,l1); pl[1] = __halves2half2(l2,l3);
    }
    CP_WAIT0();
    __syncthreads();

    for (int kt = 0; kt < nk; kt++) {
        const int cur = kt & 1;
        const bool more = (kt + 1 < nk);
        if (more) {
            int k0 = (kt + 1) * 16;
            cp16(bdst_h[cur ^ 1], bsrc_h + (size_t)k0 * ldb);
            cp16(bdst_l[cur ^ 1], bsrc_l + (size_t)k0 * ldb);
            CP_COMMIT();
            #pragma unroll
            for (int i = 0; i < 2; i++) {
                int gm = row0 + aR[i];
                va[i] = (gm < M) ? *(const float4*)(A + (size_t)gm * lda + k0 + aC[i])
                                 : make_float4(0.f, 0.f, 0.f, 0.f);
            }
        }

        {
            uint32_t ah[4][4], al[4][4], bh[4][2], bl[4][2];
            const uint32_t aoff = (uint32_t)((((lane & 15)) * ASTR + (lane >> 4) * 8) * 2);
            const uint32_t ah_base = smem_u32(&As[cur][0][0]) + aoff;
            const uint32_t al_base = smem_u32(&As[cur][1][0]) + aoff;
            #pragma unroll
            for (int mi = 0; mi < 4; mi++) {
                uint32_t o = (uint32_t)((warpM * 64 + mi * 16) * ASTR * 2);
                ldsm_x4(ah[mi], ah_base + o);
                ldsm_x4(al[mi], al_base + o);
            }
            const uint32_t boff = (uint32_t)(((lane & 15) * BSTR + (lane >> 4) * 8) * 2);
            const uint32_t bh_base = smem_u32(&Bs[cur][0][0]) + boff;
            const uint32_t bl_base = smem_u32(&Bs[cur][1][0]) + boff;
            #pragma unroll
            for (int np = 0; np < 2; np++) {
                uint32_t o = (uint32_t)((warpN * 32 + np * 16) * 2);
                uint32_t r[4];
                ldsm_x4_t(r, bh_base + o);
                bh[np*2][0] = r[0]; bh[np*2][1] = r[1];
                bh[np*2+1][0] = r[2]; bh[np*2+1][1] = r[3];
                ldsm_x4_t(r, bl_base + o);
                bl[np*2][0] = r[0]; bl[np*2][1] = r[1];
                bl[np*2+1][0] = r[2]; bl[np*2+1][1] = r[3];
            }
            #pragma unroll
            for (int mi = 0; mi < 4; mi++)
                #pragma unroll
                for (int ni = 0; ni < 4; ni++) {
                    mma16816(acc[mi][ni], ah[mi], bh[ni]);
                    mma16816(acc[mi][ni], ah[mi], bl[ni]);
                    mma16816(acc[mi][ni], al[mi], bh[ni]);
                }
        }

        if (more) {
            const int nxt = cur ^ 1;
            #pragma unroll
            for (int i = 0; i < 2; i++) {
                __half h0,h1,h2,h3,l0,l1,l2,l3;
                split2(va[i].x,h0,l0); split2(va[i].y,h1,l1);
                split2(va[i].z,h2,l2); split2(va[i].w,h3,l3);
                __half2* ph = (__half2*)&As[nxt][0][aR[i]*ASTR + aC[i]];
                ph[0] = __halves2half2(h0,h1); ph[1] = __halves2half2(h2,h3);
                __half2* pl = (__half2*)&As[nxt][1][aR[i]*ASTR + aC[i]];
                pl[0] = __halves2half2(l0,l1); pl[1] = __halves2half2(l2,l3);
            }
            CP_WAIT0();
            __syncthreads();
        }
    }

    #pragma unroll
    for (int mi = 0; mi < 4; mi++) {
        int r0 = row0 + warpM * 64 + mi * 16 + gid;
        int r1 = r0 + 8;
        #pragma unroll
        for (int ni = 0; ni < 4; ni++) {
            int c = col0 + warpN * 32 + ni * 8 + 2 * quad;
            float b0 = 0.f, b1 = 0.f;
            if (EPI >= 2) { b0 = bias[c]; b1 = bias[c + 1]; }
            if (r0 < M) {
                float x0 = acc[mi][ni][0] + b0, x1 = acc[mi][ni][1] + b1;
                if (EPI == 2) { x0 = gelu_f(x0); x1 = gelu_f(x1); }
                size_t idx = (size_t)r0 * ldc + c;
                if (EPI == 3) { C[idx] += x0; C[idx + 1] += x1; }
                else          { C[idx] = x0;  C[idx + 1] = x1; }
            }
            if (r1 < M) {
                float x0 = acc[mi][ni][2] + b0, x1 = acc[mi][ni][3] + b1;
                if (EPI == 2) { x0 = gelu_f(x0); x1 = gelu_f(x1); }
                size_t idx = (size_t)r1 * ldc + c;
                if (EPI == 3) { C[idx] += x0; C[idx + 1] += x1; }
                else          { C[idx] = x0;  C[idx + 1] = x1; }
            }
        }
    }
}

static void launch_hs(int epi, int M, int N, int K,
                      const float* A, int lda,
                      const __half* Bh, const __half* Bl, int ldb,
                      float* C, int ldc, const float* bias)
{
    dim3 grid(N / 128, (M + 127) / 128), blk(256);
    if      (epi == 0) hsgemm_kernel<0><<<grid, blk>>>(M, N, K, A, lda, Bh, Bl, ldb, C, ldc, bias);
    else if (epi == 2) hsgemm_kernel<2><<<grid, blk>>>(M, N, K, A, lda, Bh, Bl, ldb, C, ldc, bias);
    else               hsgemm_kernel<3><<<grid, blk>>>(M, N, K, A, lda, Bh, Bl, ldb, C, ldc, bias);
}

// =========================================================================
// batched split-fp16 TC GEMM for attention (unchanged from R4)
// =========================================================================
#define ASTR2 24
#define BSTR2 72

template<int TRANSB>
__global__ __launch_bounds__(256)
void attn_gemm(int M, int N, int K,
               const float* __restrict__ A, int lda, long long sA0, long long sA1,
               const float* __restrict__ B, int ldb, long long sB0, long long sB1,
               float* __restrict__ C, int ldc, long long sC0, long long sC1,
               int hdiv)
{
    __shared__ __align__(16) __half As[2][128 * ASTR2];
    __shared__ __align__(16) __half Bs[2][16 * BSTR2];

    const int z = blockIdx.z;
    const int zb = z / hdiv, zh = z - zb * hdiv;
    A += zb * sA0 + zh * sA1;
    B += zb * sB0 + zh * sB1;
    C += zb * sC0 + zh * sC1;

    const int tid = threadIdx.x;
    const int lane = tid & 31, wid = tid >> 5;
    const int warpM = wid >> 1, warpN = wid & 1;
    const int quad = lane & 3, gid = lane >> 2;
    const int row0 = blockIdx.y * 128, col0 = blockIdx.x * 64;

    float acc[2][4][4];
    #pragma unroll
    for (int i = 0; i < 2; i++)
        #pragma unroll
        for (int j = 0; j < 4; j++)
            #pragma unroll
            for (int r = 0; r < 4; r++) acc[i][j][r] = 0.f;

    const int nk = (K + 15) / 16;

    for (int kt = 0; kt < nk; kt++) {
        const int k0 = kt * 16;
        #pragma unroll
        for (int i = 0; i < 2; i++) {
            int e = tid + i * 256;
            int ar = e >> 2, ac = (e & 3) * 4;
            int gm = row0 + ar;
            #pragma unroll
            for (int j = 0; j < 4; j++) {
                int gk = k0 + ac + j;
                float v = (gm < M && gk < K) ? A[(size_t)gm * lda + gk] : 0.f;
                __half h, l; split2(v, h, l);
                As[0][ar * ASTR2 + ac + j] = h;
                As[1][ar * ASTR2 + ac + j] = l;
            }
        }
        if (TRANSB) {
            int nloc = tid >> 2, kc = (tid & 3) * 4;
            int gn = col0 + nloc;
            #pragma unroll
            for (int j = 0; j < 4; j++) {
                int gk = k0 + kc + j;
                float v = (gn < N && gk < K) ? B[(size_t)gn * ldb + gk] : 0.f;
                __half h, l; split2(v, h, l);
                Bs[0][(kc + j) * BSTR2 + nloc] = h;
                Bs[1][(kc + j) * BSTR2 + nloc] = l;
            }
        } else {
            int kl = tid >> 4, nc = (tid & 15) * 4;
            int gk = k0 + kl;
            #pragma unroll
            for (int j = 0; j < 4; j++) {
                int gn = col0 + nc + j;
                float v = (gk < K && gn < N) ? B[(size_t)gk * ldb + gn] : 0.f;
                __half h, l; split2(v, h, l);
                Bs[0][kl * BSTR2 + nc + j] = h;
                Bs[1][kl * BSTR2 + nc + j] = l;
            }
        }
        __syncthreads();

        {
            uint32_t ah[2][4], al[2][4], bh[4][2], bl[4][2];
            const uint32_t aoff = (uint32_t)(((lane & 15) * ASTR2 + (lane >> 4) * 8) * 2);
            const uint32_t ah_base = smem_u32(&As[0][0]) + aoff;
            const uint32_t al_base = smem_u32(&As[1][0]) + aoff;
            #pragma unroll
            for (int mi = 0; mi < 2; mi++) {
                uint32_t o = (uint32_t)((warpM * 32 + mi * 16) * ASTR2 * 2);
                ldsm_x4(ah[mi], ah_base + o);
                ldsm_x4(al[mi], al_base + o);
            }
            const uint32_t boff = (uint32_t)(((lane & 15) * BSTR2 + (lane >> 4) * 8) * 2);
            const uint32_t bh_base = smem_u32(&Bs[0][0]) + boff;
            const uint32_t bl_base = smem_u32(&Bs[1][0]) + boff;
            #pragma unroll
            for (int np = 0; np < 2; np++) {
                uint32_t o = (uint32_t)((warpN * 32 + np * 16) * 2);
                uint32_t r[4];
                ldsm_x4_t(r, bh_base + o);
                bh[np*2][0] = r[0]; bh[np*2][1] = r[1];
                bh[np*2+1][0] = r[2]; bh[np*2+1][1] = r[3];
                ldsm_x4_t(r, bl_base + o);
                bl[np*2][0] = r[0]; bl[np*2][1] = r[1];
                bl[np*2+1][0] = r[2]; bl[np*2+1][1] = r[3];
            }
            #pragma unroll
            for (int mi = 0; mi < 2; mi++)
                #pragma unroll
                for (int ni = 0; ni < 4; ni++) {
                    mma16816(acc[mi][ni], ah[mi], bh[ni]);
                    mma16816(acc[mi][ni], ah[mi], bl[ni]);
                    mma16816(acc[mi][ni], al[mi], bh[ni]);
                }
        }
        __syncthreads();
    }

    #pragma unroll
    for (int mi = 0; mi < 2; mi++) {
        int r0 = row0 + warpM * 32 + mi * 16 + gid;
        int r1 = r0 + 8;
        #pragma unroll
        for (int ni = 0; ni < 4; ni++) {
            int c = col0 + warpN * 32 + ni * 8 + 2 * quad;
            if (r0 < M) {
                if (c < N)     C[(size_t)r0 * ldc + c]     = acc[mi][ni][0];
                if (c + 1 < N) C[(size_t)r0 * ldc + c + 1] = acc[mi][ni][1];
            }
            if (r1 < M) {
                if (c < N)     C[(size_t)r1 * ldc + c]     = acc[mi][ni][2];
                if (c + 1 < N) C[(size_t)r1 * ldc + c + 1] = acc[mi][ni][3];
            }
        }
    }
}

// =========================================================================
// mega weight split (QKV packed + wo + mlp1 + mlp2 + convT)
// =========================================================================
__global__ void split_all_kernel(const float* __restrict__ wq, const float* __restrict__ wk,
                                 const float* __restrict__ wv, const float* __restrict__ wo,
                                 const float* __restrict__ m1, const float* __restrict__ m2,
                                 const float* __restrict__ cw,
                                 __half* __restrict__ bh, __half* __restrict__ bl)
{
    const long long QKV4 = 3LL * SZ_ATT / 4;
    const long long WO4  = (long long)SZ_ATT / 4;
    const long long M4   = (long long)SZ_MLP / 4;
    const long long TOT4 = QKV4 + WO4 + 2 * M4;

    long long i = (long long)blockIdx.x * 256 + threadIdx.x;

    if (i < QKV4) {
        int w = (int)(i / (SZ_ATT / 4));
        long long j = i - (long long)w * (SZ_ATT / 4);
        const float* src = (w == 0) ? wq : (w == 1) ? wk : wv;
        float4 v = ((const float4*)src)[j];
        long long s = 4 * j;
        int L = (int)(s / ((long long)DVAL * DVAL));
        int r = (int)(s - (long long)L * DVAL * DVAL);
        int k = r / DVAL, n = r - k * DVAL;
        long long d = OFF_QKV + (long long)L * DVAL * QKVN + (long long)k * QKVN + w * DVAL + n;
        __half h0,h1,h2,h3,l0,l1,l2,l3;
        split2(v.x,h0,l0); split2(v.y,h1,l1); split2(v.z,h2,l2); split2(v.w,h3,l3);
        __half2* ph = (__half2*)(bh + d);
        ph[0] = __halves2half2(h0,h1); ph[1] = __halves2half2(h2,h3);
        __half2* pl = (__half2*)(bl + d);
        pl[0] = __halves2half2(l0,l1); pl[1] = __halves2half2(l2,l3);
        return;
    }
    if (i < TOT4) {
        long long i2 = i - QKV4;
        const float* src; long long off, j;
        if (i2 < WO4)            { src = wo; off = OFF_WO; j = i2; }
        else if (i2 < WO4 + M4)  { src = m1; off = OFF_M1; j = i2 - WO4; }
        else                     { src = m2; off = OFF_M2; j = i2 - WO4 - M4; }
        float4 v = ((const float4*)src)[j];
        long long d = off + 4 * j;
        __half h0,h1,h2,h3,l0,l1,l2,l3;
        split2(v.x,h0,l0); split2(v.y,h1,l1); split2(v.z,h2,l2); split2(v.w,h3,l3);
        __half2* ph = (__half2*)(bh + d);
        ph[0] = __halves2half2(h0,h1); ph[1] = __halves2half2(h2,h3);
        __half2* pl = (__half2*)(bl + d);
        pl[0] = __halves2half2(l0,l1); pl[1] = __halves2half2(l2,l3);
        return;
    }
    long long idx = i - TOT4;
    if (idx < (long long)DVAL * DVAL) {
        int k = (int)(idx / DVAL), n = (int)(idx % DVAL);
        float x = cw[(long long)n * DVAL + k];
        __half h, l; split2(x, h, l);
        bh[OFF_WT + idx] = h;
        bl[OFF_WT + idx] = l;
    }
}

// ---------------- LayerNorm (warp-shuffle reductions, 3 syncs) ----------------
__global__ void ln_kernel(const float* __restrict__ in, float* __restrict__ out,
                          const float* __restrict__ w, const float* __restrict__ b)
{
    __shared__ float red[8];
    int row = blockIdx.x;
    int tid = threadIdx.x;
    int lane = tid & 31, wd = tid >> 5;
    const float* x = in + (long long)row * DVAL;

    float v0 = x[tid], v1 = x[tid + 256], v2 = x[tid + 512];
    float s = v0 + v1 + v2;
    #pragma unroll
    for (int o = 16; o > 0; o >>= 1) s += __shfl_xor_sync(0xffffffffu, s, o);
    if (lane == 0) red[wd] = s;
    __syncthreads();
    float mu = (red[0] + red[1] + red[2] + red[3] + red[4] + red[5] + red[6] + red[7])
               * (1.0f / 768.0f);

    float d0 = v0 - mu, d1 = v1 - mu, d2 = v2 - mu;
    float s2 = d0 * d0 + d1 * d1 + d2 * d2;
    #pragma unroll
    for (int o = 16; o > 0; o >>= 1) s2 += __shfl_xor_sync(0xffffffffu, s2, o);
    __syncthreads();
    if (lane == 0) red[wd] = s2;
    __syncthreads();
    float rs = rsqrtf((red[0] + red[1] + red[2] + red[3] + red[4] + red[5] + red[6] + red[7])
                      * (1.0f / 768.0f) + 1e-5f);

    float* y = out + (long long)row * DVAL;
    y[tid]       = d0 * rs * w[tid]       + b[tid];
    y[tid + 256] = d1 * rs * w[tid + 256] + b[tid + 256];
    y[tid + 512] = d2 * rs * w[tid + 512] + b[tid + 512];
}

// ---------------- softmax (197), warp per row ----------------
__global__ void softmax_kernel(float* __restrict__ s)
{
    int row = blockIdx.x * 8 + (threadIdx.x >> 5);
    if (row >= BVAL * HEADS * NTOK) return;
    int lane = threadIdx.x & 31;
    float* p = s + (long long)row * NTOK;
    const float scale = 0.125f;

    float vals[7];
    float mx = -1e30f;
    #pragma unroll
    for (int i = 0; i < 7; i++) {
        int c = lane + i * 32;
        float v = (c < NTOK) ? p[c] * scale : -1e30f;
        vals[i] = v;
        mx = fmaxf(mx, v);
    }
    #pragma unroll
    for (int o = 16; o > 0; o >>= 1) mx = fmaxf(mx, __shfl_xor_sync(0xffffffffu, mx, o));

    float sum = 0.f;
    #pragma unroll
    for (int i = 0; i < 7; i++) {
        int c = lane + i * 32;
        float e = (c < NTOK) ? expf(vals[i] - mx) : 0.f;
        vals[i] = e;
        sum += e;
    }
    #pragma unroll
    for (int o = 16; o > 0; o >>= 1) sum += __shfl_xor_sync(0xffffffffu, sum, o);
    float inv = 1.0f / sum;

    #pragma unroll
    for (int i = 0; i < 7; i++) {
        int c = lane + i * 32;
        if (c < NTOK) p[c] = vals[i] * inv;
    }
}

// ---------------- patch-embed helpers ----------------
__global__ void im2col_kernel(const float* __restrict__ x)
{
    long long idx = (long long)blockIdx.x * blockDim.x + threadIdx.x;
    if (idx >= (long long)MPATCH * DVAL) return;
    int col = (int)(idx % DVAL);
    long long r = idx / DVAL;
    int p = (int)(r % NPATCH);
    int b = (int)(r / NPATCH);
    int c = col >> 8;
    int rem = col & 255;
    int i = rem >> 4, j = rem & 15;
    int py = p / 14, px = p % 14;
    g_col[idx] = x[(((long long)b * 3 + c) * 224 + py * 16 + i) * 224 + px * 16 + j];
}

__global__ void assemble_tok_kernel(const float* __restrict__ patch,
                                    const float* __restrict__ cls,
                                    const float* __restrict__ pos)
{
    long long idx = (long long)blockIdx.x * blockDim.x + threadIdx.x;
    if (idx >= (long long)MTOK * DVAL) return;
    int d = (int)(idx % DVAL);
    long long r = idx / DVAL;
    int n = (int)(r % NTOK);
    int b = (int)(r / NTOK);
    float v;
    if (n == 0) v = cls[d];
    else        v = patch[((long long)b * NPATCH + (n - 1)) * DVAL + d];
    g_tok[idx] = v + pos[n * DVAL + d];
}

// ---------------- head ----------------
__global__ void head_kernel(const float* __restrict__ tok,
                            const float* __restrict__ fw, const float* __restrict__ fb,
                            const float* __restrict__ hw, const float* __restrict__ hb,
                            const float* __restrict__ h1w, const float* __restrict__ h1b,
                            const float* __restrict__ h2w, const float* __restrict__ h2b,
                            float* __restrict__ out)
{
    __shared__ float cbuf[DVAL];
    __shared__ float hid[MLPD];
    __shared__ float red[256];
    int b = blockIdx.x, tid = threadIdx.x;
    const float* t = tok + (long long)b * NTOK * DVAL;

    float v0 = t[tid], v1 = t[tid + 256], v2 = t[tid + 512];
    red[tid] = v0 + v1 + v2; __syncthreads();
    for (int o = 128; o > 0; o >>= 1) { if (tid < o) red[tid] += red[tid + o]; __syncthreads(); }
    float mu = red[0] * (1.0f / 768.0f); __syncthreads();
    float d0 = v0 - mu, d1 = v1 - mu, d2 = v2 - mu;
    red[tid] = d0 * d0 + d1 * d1 + d2 * d2; __syncthreads();
    for (int o = 128; o > 0; o >>= 1) { if (tid < o) red[tid] += red[tid + o]; __syncthreads(); }
    float rs = rsqrtf(red[0] * (1.0f / 768.0f) + 1e-5f); __syncthreads();
    float u0 = d0 * rs * fw[tid]       + fb[tid];
    float u1 = d1 * rs * fw[tid + 256] + fb[tid + 256];
    float u2 = d2 * rs * fw[tid + 512] + fb[tid + 512];

    red[tid] = u0 + u1 + u2; __syncthreads();
    for (int o = 128; o > 0; o >>= 1) { if (tid < o) red[tid] += red[tid + o]; __syncthreads(); }
    mu = red[0] * (1.0f / 768.0f); __syncthreads();
    d0 = u0 - mu; d1 = u1 - mu; d2 = u2 - mu;
    red[tid] = d0 * d0 + d1 * d1 + d2 * d2; __syncthreads();
    for (int o = 128; o > 0; o >>= 1) { if (tid < o) red[tid] += red[tid + o]; __syncthreads(); }
    rs = rsqrtf(red[0] * (1.0f / 768.0f) + 1e-5f); __syncthreads();
    cbuf[tid]       = d0 * rs * hw[tid]       + hb[tid];
    cbuf[tid + 256] = d1 * rs * hw[tid + 256] + hb[tid + 256];
    cbuf[tid + 512] = d2 * rs * hw[tid + 512] + hb[tid + 512];
    __syncthreads();

    for (int j = tid; j < MLPD; j += 256) {
        float sacc = h1b[j];
        for (int d = 0; d < DVAL; d++)
            sacc = fmaf(cbuf[d], h1w[(long long)d * MLPD + j], sacc);
        hid[j] = gelu_f(sacc);
    }
    __syncthreads();

    for (int c2 = 0; c2 < 2; c2++) {
        float part = 0.f;
        for (int j = tid; j < MLPD; j += 256)
            part = fmaf(hid[j], h2w[j * 2 + c2], part);
        red[tid] = part; __syncthreads();
        for (int o = 128; o > 0; o >>= 1) { if (tid < o) red[tid] += red[tid + o]; __syncthreads(); }
        if (tid == 0) out[b * 2 + c2] = red[0] + h2b[c2];
        __syncthreads();
    }
}

extern "C" void kernel_launch(void* const* d_in, const int* in_sizes, int n_in,
                              void* d_out, int out_size)
{
    const float* x         = (const float*)d_in[0];
    const float* conv_w    = (const float*)d_in[1];
    const float* conv_b    = (const float*)d_in[2];
    const float* cls_token = (const float*)d_in[3];
    const float* pos_embed = (const float*)d_in[4];
    const float* ln1_w     = (const float*)d_in[5];
    const float* ln1_b     = (const float*)d_in[6];
    const float* wq        = (const float*)d_in[7];
    const float* wk        = (const float*)d_in[8];
    const float* wv        = (const float*)d_in[9];
    const float* wo_w      = (const float*)d_in[10];
    const float* wo_b      = (const float*)d_in[11];
    const float* ln2_w     = (const float*)d_in[12];
    const float* ln2_b     = (const float*)d_in[13];
    const float* mlp1_w    = (const float*)d_in[14];
    const float* mlp1_b    = (const float*)d_in[15];
    const float* mlp2_w    = (const float*)d_in[16];
    const float* mlp2_b    = (const float*)d_in[17];
    const float* fnorm_w   = (const float*)d_in[18];
    const float* fnorm_b   = (const float*)d_in[19];
    const float* hln_w     = (const float*)d_in[20];
    const float* hln_b     = (const float*)d_in[21];
    const float* h1_w      = (const float*)d_in[22];
    const float* h1_b      = (const float*)d_in[23];
    const float* h2_w      = (const float*)d_in[24];
    const float* h2_b      = (const float*)d_in[25];

    float *tokp, *hp, *qkvp, *ctxp, *scp, *hidp, *colp;
    __half *bh, *bl;
    cudaGetSymbolAddress((void**)&tokp, g_tok);
    cudaGetSymbolAddress((void**)&hp,   g_hbuf);
    cudaGetSymbolAddress((void**)&qkvp, g_qkv);
    cudaGetSymbolAddress((void**)&ctxp, g_ctx);
    cudaGetSymbolAddress((void**)&scp,  g_scores);
    cudaGetSymbolAddress((void**)&hidp, g_hid);
    cudaGetSymbolAddress((void**)&colp, g_col);
    cudaGetSymbolAddress((void**)&bh,   g_bh);
    cudaGetSymbolAddress((void**)&bl,   g_bl);

    {
        long long tot = 3LL*SZ_ATT/4 + (long long)SZ_ATT/4 + 2LL*SZ_MLP/4 + (long long)DVAL*DVAL;
        int blocks = (int)((tot + 255) / 256);
        split_all_kernel<<<blocks, 256>>>(wq, wk, wv, wo_w, mlp1_w, mlp2_w, conv_w, bh, bl);
    }

    im2col_kernel<<<(int)(((long long)MPATCH * DVAL + 255) / 256), 256>>>(x);
    launch_hs(2, MPATCH, DVAL, DVAL, colp, DVAL, bh + OFF_WT, bl + OFF_WT, DVAL, ctxp, DVAL, conv_b);
    assemble_tok_kernel<<<(int)(((long long)MTOK * DVAL + 255) / 256), 256>>>(ctxp, cls_token, pos_embed);

    const long long DQ = (long long)DVAL * QKVN;
    const long long D2 = (long long)DVAL * DVAL;
    const long long DM = (long long)DVAL * MLPD;

    for (int L = 0; L < DEPTH; L++) {
        ln_kernel<<<MTOK, 256>>>(tokp, hp, ln1_w + L * DVAL, ln1_b + L * DVAL);
        launch_hs(0, MTOK, QKVN, DVAL, hp, DVAL,
                  bh + OFF_QKV + L * DQ, bl + OFF_QKV + L * DQ, QKVN, qkvp, QKVN, nullptr);

        {
            dim3 grid((NTOK + 63) / 64, (NTOK + 127) / 128, BVAL * HEADS);
            attn_gemm<1><<<grid, 256>>>(NTOK, NTOK, DKV,
                qkvp,             QKVN, (long long)NTOK * QKVN, DKV,
                qkvp + DVAL,      QKVN, (long long)NTOK * QKVN, DKV,
                scp,              NTOK, (long long)HEADS * NNSC, NNSC,
                HEADS);
        }
        softmax_kernel<<<(BVAL * HEADS * NTOK) / 8, 256>>>(scp);
        {
            dim3 grid(1, (NTOK + 127) / 128, BVAL * HEADS);
            attn_gemm<0><<<grid, 256>>>(NTOK, DKV, NTOK,
                scp,              NTOK, (long long)HEADS * NNSC, NNSC,
                qkvp + 2 * DVAL,  QKVN, (long long)NTOK * QKVN, DKV,
                ctxp,             DVAL, (long long)NTOK * DVAL, DKV,
                HEADS);
        }
        launch_hs(3, MTOK, DVAL, DVAL, ctxp, DVAL,
                  bh + OFF_WO + L * D2, bl + OFF_WO + L * D2, DVAL, tokp, DVAL, wo_b + L * DVAL);
        ln_kernel<<<MTOK, 256>>>(tokp, hp, ln2_w + L * DVAL, ln2_b + L * DVAL);
        launch_hs(2, MTOK, MLPD, DVAL, hp, DVAL,
                  bh + OFF_M1 + L * DM, bl + OFF_M1 + L * DM, MLPD, hidp, MLPD, mlp1_b + L * MLPD);
        launch_hs(3, MTOK, DVAL, MLPD, hidp, MLPD,
                  bh + OFF_M2 + L * DM, bl + OFF_M2 + L * DM, DVAL, tokp, DVAL, mlp2_b + L * DVAL);
    }

    head_kernel<<<BVAL, 256>>>(tokp, fnorm_w, fnorm_b, hln_w, hln_b,
                               h1_w, h1_b, h2_w, h2_b, (float*)d_out);
}